// round 4
// baseline (speedup 1.0000x reference)
#include <cuda_runtime.h>
#include <cuda_bf16.h>
#include <math.h>

// DIM=300 (K padded to 304 = 19 k16 stages), B=16, T=2000, Tq=30, Topt=16
#define KP 304
#define NSTAGE 19
// CE padded row layout (128-aligned range starts): 0,32000,48000,56064,59392; M=60672

typedef __nv_bfloat16 bf16;

// ---------------- scratch ----------------
__device__ float g_art[32000 * 300];
__device__ bf16  g_xsh[60672 * KP], g_xsl[60672 * KP];   // rows 0..32000 = article split
__device__ float g_h[60672 * 300];
__device__ float g_z[32000 * 300];
__device__ float g_o[32000 * 300];
__device__ bf16  g_ench[32768 * KP], g_encl[32768 * KP]; // rows b*2048+t
__device__ float g_s1[32768 * 32];                       // attn1 scores
__device__ float g_qf[480 * 300];
__device__ bf16  g_qh[512 * KP], g_ql[512 * KP];
__device__ float g_optf[1024 * 300];
__device__ bf16  g_opth[1024 * KP], g_optl[1024 * KP];
__device__ float g_k2[1024 * 300], g_k3[1024 * 300];
__device__ bf16  g_kb1h[16 * 64 * KP], g_kb1l[16 * 64 * KP]; // f1 keys per batch (rows 30..63 zero)
__device__ float g_QK[16 * 30 * 128];
__device__ float g_scA[16 * 40 * 300], g_scB[16 * 40 * 300], g_scC[16 * 40 * 300];
__device__ float g_cm[4 * 16 * 2 * 16];
// weight slots [320][KP]: 0-4 ce, 5 Wz, 6 Wo, 7 f1, 8 f2, 9 f3
#define WSLOT (320 * KP)
__device__ bf16 g_wh[10 * WSLOT], g_wl[10 * WSLOT];

// ---------------- helpers ----------------
__device__ __forceinline__ void split2(float x, bf16& h, bf16& l) {
    h = __float2bfloat16(x);
    l = __float2bfloat16(x - __bfloat162float(h));
}
__device__ __forceinline__ void cp16(void* s, const void* g) {
    unsigned sa = (unsigned)__cvta_generic_to_shared(s);
    asm volatile("cp.async.cg.shared.global [%0], [%1], 16;" :: "r"(sa), "l"(g));
}
__device__ __forceinline__ void mma16816(float* c, const unsigned* a, const unsigned* b) {
    asm volatile(
        "mma.sync.aligned.m16n8k16.row.col.f32.bf16.bf16.f32 "
        "{%0,%1,%2,%3}, {%4,%5,%6,%7}, {%8,%9}, {%0,%1,%2,%3};\n"
        : "+f"(c[0]), "+f"(c[1]), "+f"(c[2]), "+f"(c[3])
        : "r"(a[0]), "r"(a[1]), "r"(a[2]), "r"(a[3]), "r"(b[0]), "r"(b[1]));
}

// ---------------- weight prep ----------------
__global__ void split_w(const float* __restrict__ src, int slotBase, int count) {
    int i = blockIdx.x * blockDim.x + threadIdx.x;
    if (i >= count) return;
    int slot = slotBase + i / 90000;
    int rem = i % 90000;
    int n = rem / 300, k = rem - n * 300;
    bf16 h, l; split2(src[i], h, l);
    int o = slot * WSLOT + n * KP + k;
    g_wh[o] = h; g_wl[o] = l;
}

// ---------------- embedding gather + split ----------------
__global__ void gather_split(const int* __restrict__ idx, const float* __restrict__ emb,
                             int sel, int rowOff, int nrows) {
    int i = blockIdx.x * blockDim.x + threadIdx.x;
    if (i >= nrows * 300) return;
    int r = i / 300, d = i - r * 300;
    float x = emb[idx[r] * 300 + d];
    int R = rowOff + r;
    bf16 hb, lb; split2(x, hb, lb);
    if (sel == 0) {          // article: fp32 + split straight into xs rows (r=1 block)
        g_art[R * 300 + d] = x;
        g_xsh[R * KP + d] = hb; g_xsl[R * KP + d] = lb;
    } else if (sel == 1) {   // question
        g_qf[R * 300 + d] = x;
        g_qh[R * KP + d] = hb; g_ql[R * KP + d] = lb;
    } else {                 // options
        g_optf[R * 300 + d] = x;
        g_opth[R * KP + d] = hb; g_optl[R * KP + d] = lb;
    }
}

// ---------------- group sums for r>=2 ranges ----------------
__global__ void xs_kernel() {
    int i = blockIdx.x * blockDim.x + threadIdx.x;
    if (i >= 28672 * 300) return;
    int R = 32000 + i / 300, d = i % 300;
    float s;
    if (R < 48000) {
        int L = R - 32000, b = L / 1000, g = L - b * 1000;
        int base = (b * 2000 + g * 2) * 300 + d;
        s = g_art[base] + g_art[base + 300];
    } else if (R < 56000) {
        int L = R - 48000, b = L / 500, g = L - b * 500;
        int base = (b * 2000 + g * 4) * 300 + d;
        s = 0.f;
        #pragma unroll
        for (int j = 0; j < 4; j++) s += g_art[base + j * 300];
    } else if (R < 56064) return;
    else if (R < 59264) {
        int L = R - 56064, b = L / 200, g = L - b * 200;
        int base = (b * 2000 + g * 10) * 300 + d;
        s = 0.f;
        #pragma unroll
        for (int j = 0; j < 10; j++) s += g_art[base + j * 300];
    } else if (R < 59392) return;
    else {
        int L = R - 59392, b = L / 80, g = L - b * 80;
        int base = (b * 2000 + g * 25) * 300 + d;
        s = 0.f;
        #pragma unroll
        for (int j = 0; j < 25; j++) s += g_art[base + j * 300];
    }
    bf16 h, l; split2(s, h, l);
    g_xsh[R * KP + d] = h;
    g_xsl[R * KP + d] = l;
}

// ---------------- tensor-core GEMM ----------------
// C = act(A(M,300) @ W(300,300)^T + bias); bf16 2-split (hh+hl+lh).
// wmode: 0 slot weights, 1 CE per-range, 2 per-batch f1 keys (bm>>11).
// act: 0 none /1 relu /2 tanh (fp32 C, stride 300); 3 scores (fp32, stride 32, n<32, no bias);
//      4 key-split (add bias, split -> g_kb1, m<480)
#define SAST 24
__global__ void __launch_bounds__(256) gemm_mma(int Asel, int wslot, const float* __restrict__ bias,
                                                int Csel, int M, int act, int wmode) {
    __shared__ __align__(16) bf16 sA[2][2][128 * SAST];
    __shared__ __align__(16) bf16 sB[2][2][64 * SAST];

    const bf16 *Ah, *Al;
    switch (Asel) {
        case 0: Ah = g_xsh;  Al = g_xsl;  break;
        case 1: Ah = g_qh;   Al = g_ql;   break;
        case 2: Ah = g_opth; Al = g_optl; break;
        default: Ah = g_ench; Al = g_encl; break;
    }
    float* C;
    switch (Csel) {
        case 0: C = g_h;  break;
        case 1: C = g_z;  break;
        case 2: C = g_o;  break;
        case 3: C = g_k2; break;
        case 4: C = g_k3; break;
        default: C = g_s1; break;
    }
    int bm = blockIdx.y * 128, bn = blockIdx.x * 64;
    const bf16 *Wh, *Wl;
    if (wmode == 1) {
        int slot = (bm < 32000) ? 0 : (bm < 48000) ? 1 : (bm < 56064) ? 2 : (bm < 59392) ? 3 : 4;
        bias += slot * 300;
        Wh = g_wh + slot * WSLOT; Wl = g_wl + slot * WSLOT;
    } else if (wmode == 2) {
        int b = bm >> 11;
        Wh = g_kb1h + b * 64 * KP; Wl = g_kb1l + b * 64 * KP;
    } else {
        Wh = g_wh + wslot * WSLOT; Wl = g_wl + wslot * WSLOT;
    }

    int tid = threadIdx.x;
    int lane = tid & 31, warp = tid >> 5;
    int wm = warp & 3, wn = warp >> 2;

    auto issue = [&](int s, int buf) {
        int kt = s * 16;
        int row = tid >> 1, kh = (tid & 1) * 8;
        cp16(&sA[buf][0][row * SAST + kh], Ah + (size_t)(bm + row) * KP + kt + kh);
        cp16(&sA[buf][1][row * SAST + kh], Al + (size_t)(bm + row) * KP + kt + kh);
        if (tid < 128) {
            int br = tid >> 1, bkh = (tid & 1) * 8;
            cp16(&sB[buf][0][br * SAST + bkh], Wh + (size_t)(bn + br) * KP + kt + bkh);
        } else {
            int t = tid - 128;
            int br = t >> 1, bkh = (t & 1) * 8;
            cp16(&sB[buf][1][br * SAST + bkh], Wl + (size_t)(bn + br) * KP + kt + bkh);
        }
        asm volatile("cp.async.commit_group;");
    };

    float acc[2][4][4];
    #pragma unroll
    for (int mi = 0; mi < 2; mi++)
        #pragma unroll
        for (int ni = 0; ni < 4; ni++)
            #pragma unroll
            for (int j = 0; j < 4; j++) acc[mi][ni][j] = 0.f;

    issue(0, 0);
    issue(1, 1);
    asm volatile("cp.async.wait_group 1;");
    __syncthreads();

    int r0 = wm * 32 + (lane >> 2);
    int kc = lane & 3;
    int nb0 = wn * 32 + (lane >> 2);

    for (int s = 0; s < NSTAGE; s++) {
        int buf = s & 1;
        const unsigned* A32h = (const unsigned*)sA[buf][0];
        const unsigned* A32l = (const unsigned*)sA[buf][1];
        const unsigned* B32h = (const unsigned*)sB[buf][0];
        const unsigned* B32l = (const unsigned*)sB[buf][1];
        unsigned ah[2][4], al[2][4], bh[4][2], bl[4][2];
        #pragma unroll
        for (int mi = 0; mi < 2; mi++) {
            int r = r0 + mi * 16;
            int i0 = r * (SAST / 2) + kc;
            int i1 = (r + 8) * (SAST / 2) + kc;
            ah[mi][0] = A32h[i0];     ah[mi][1] = A32h[i1];
            ah[mi][2] = A32h[i0 + 4]; ah[mi][3] = A32h[i1 + 4];
            al[mi][0] = A32l[i0];     al[mi][1] = A32l[i1];
            al[mi][2] = A32l[i0 + 4]; al[mi][3] = A32l[i1 + 4];
        }
        #pragma unroll
        for (int ni = 0; ni < 4; ni++) {
            int n = nb0 + ni * 8;
            int i0 = n * (SAST / 2) + kc;
            bh[ni][0] = B32h[i0]; bh[ni][1] = B32h[i0 + 4];
            bl[ni][0] = B32l[i0]; bl[ni][1] = B32l[i0 + 4];
        }
        #pragma unroll
        for (int mi = 0; mi < 2; mi++)
            #pragma unroll
            for (int ni = 0; ni < 4; ni++) {
                mma16816(acc[mi][ni], ah[mi], bh[ni]);
                mma16816(acc[mi][ni], ah[mi], bl[ni]);
                mma16816(acc[mi][ni], al[mi], bh[ni]);
            }
        __syncthreads();
        if (s + 2 < NSTAGE) {
            issue(s + 2, buf);
            asm volatile("cp.async.wait_group 1;");
        } else {
            asm volatile("cp.async.wait_group 0;");
        }
        __syncthreads();
    }

    // epilogue
    #pragma unroll
    for (int mi = 0; mi < 2; mi++) {
        int mrow = bm + wm * 32 + mi * 16 + (lane >> 2);
        #pragma unroll
        for (int ni = 0; ni < 4; ni++) {
            int ncol = bn + wn * 32 + ni * 8 + 2 * (lane & 3);
            #pragma unroll
            for (int rr = 0; rr < 2; rr++) {
                int m = mrow + rr * 8;
                #pragma unroll
                for (int cc = 0; cc < 2; cc++) {
                    int n = ncol + cc;
                    float v = acc[mi][ni][rr * 2 + cc];
                    if (act == 3) {
                        if (m < M && n < 32) C[(size_t)m * 32 + n] = v;
                    } else if (act == 4) {
                        if (m < 480 && n < 300) {
                            v += __ldg(&bias[n]);
                            int b = m / 30, w = m - b * 30;
                            bf16 hb, lb; split2(v, hb, lb);
                            int o = (b * 64 + w) * KP + n;
                            g_kb1h[o] = hb; g_kb1l[o] = lb;
                        }
                    } else {
                        if (m < M && n < 300) {
                            v += __ldg(&bias[n]);
                            if (act == 1) v = fmaxf(v, 0.f);
                            else if (act == 2) v = tanhf(v);
                            C[(size_t)m * 300 + n] = v;
                        }
                    }
                }
            }
        }
    }
}

// ---------------- fused gate evaluation ----------------
__device__ __forceinline__ float gate_val(int b, int t, int d, const float* m1,
                                          const float* mb1, const float* m2, float mb2) {
    float y0 = g_h[(b * 2000 + t) * 300 + d];
    float y1 = g_h[(32000 + b * 1000 + (t >> 1)) * 300 + d] * 0.5f;
    float y2 = g_h[(48000 + b * 500 + (t >> 2)) * 300 + d] * 0.25f;
    float y3 = g_h[(56064 + b * 200 + t / 10) * 300 + d] * (1.0f / 10.0f);
    float y4 = g_h[(59392 + b * 80 + t / 25) * 300 + d] * (1.0f / 25.0f);
    float acc = mb2;
    #pragma unroll
    for (int k = 0; k < 3; k++) {
        float hk = mb1[k] + m1[k * 5] * y0 + m1[k * 5 + 1] * y1 + m1[k * 5 + 2] * y2
                 + m1[k * 5 + 3] * y3 + m1[k * 5 + 4] * y4;
        acc += m2[k] * fmaxf(hk, 0.f);
    }
    return fmaxf(acc, 0.f);
}

// ---------------- chunked linear scan (gate fused) ----------------
__global__ void scanA_kernel(const float* __restrict__ mr1W, const float* __restrict__ mr1b,
                             const float* __restrict__ mr2W, const float* __restrict__ mr2b) {
    int ch = blockIdx.x, b = blockIdx.y, d = threadIdx.x;
    float m1[15], mb1[3], m2[3];
    #pragma unroll
    for (int k = 0; k < 15; k++) m1[k] = __ldg(&mr1W[k]);
    #pragma unroll
    for (int k = 0; k < 3; k++) { mb1[k] = __ldg(&mr1b[k]); m2[k] = __ldg(&mr2W[k]); }
    float mb2 = __ldg(mr2b);
    int t0 = ch * 50;
    float a = 1.f, bb = 0.f;
    for (int j = 0; j < 50; j++) {
        float g = gate_val(b, t0 + j, d, m1, mb1, m2, mb2);
        float z = g_z[(b * 2000 + t0 + j) * 300 + d];
        a *= g;
        bb = g * (bb - z) + z;
    }
    int o = (b * 40 + ch) * 300 + d;
    g_scA[o] = a;
    g_scB[o] = bb;
}
__global__ void scanB_kernel() {
    int b = blockIdx.x, d = threadIdx.x;
    float c = 0.f;
    for (int ch = 0; ch < 40; ch++) {
        int o = (b * 40 + ch) * 300 + d;
        g_scC[o] = c;
        c = g_scA[o] * c + g_scB[o];
    }
}
__global__ void scanC_kernel(const float* __restrict__ mr1W, const float* __restrict__ mr1b,
                             const float* __restrict__ mr2W, const float* __restrict__ mr2b) {
    int ch = blockIdx.x, b = blockIdx.y, d = threadIdx.x;
    float m1[15], mb1[3], m2[3];
    #pragma unroll
    for (int k = 0; k < 15; k++) m1[k] = __ldg(&mr1W[k]);
    #pragma unroll
    for (int k = 0; k < 3; k++) { mb1[k] = __ldg(&mr1b[k]); m2[k] = __ldg(&mr2W[k]); }
    float mb2 = __ldg(mr2b);
    float c = g_scC[(b * 40 + ch) * 300 + d];
    int t0 = ch * 50;
    for (int j = 0; j < 50; j++) {
        int t = t0 + j;
        float g = gate_val(b, t, d, m1, mb1, m2, mb2);
        float z = g_z[(b * 2000 + t) * 300 + d];
        c = g * (c - z) + z;
        float enc = g_o[(b * 2000 + t) * 300 + d] * c;
        bf16 hb, lb; split2(enc, hb, lb);
        int o = (b * 2048 + t) * KP + d;
        g_ench[o] = hb; g_encl[o] = lb;
    }
}

// ---------------- QK precompute: QK[b][w1][kk] = q[b,w1,:] . key[b,kk,:] ----------------
__global__ void qk_kernel() {
    __shared__ float sq[30 * 300];
    int b = blockIdx.x, tid = threadIdx.x;
    for (int i = tid; i < 30 * 300; i += 256) sq[i] = g_qf[b * 30 * 300 + i];
    __syncthreads();
    for (int idx = tid; idx < 30 * 128; idx += 256) {
        int w1 = idx >> 7, kk = idx & 127;
        int proj = kk >> 6, r = kk & 63;
        int opt = r >> 4, w = r & 15;
        const float* key = (proj ? g_k3 : g_k2) + ((size_t)((opt * 16 + b) * 16 + w)) * 300;
        float s = 0.f;
        const float* qq = sq + w1 * 300;
        for (int dd = 0; dd < 300; dd++) s += qq[dd] * key[dd];
        g_QK[b * 3840 + idx] = s;
    }
}

// ---------------- fused: softmax30 -> P.QK -> group softmax16 -> column sums ----------------
__global__ void attn_fused() {
    __shared__ float sQK[30 * 128];
    __shared__ float sacc[128];
    int ch = blockIdx.x, b = blockIdx.y;
    int tid = threadIdx.x, warp = tid >> 5, lane = tid & 31;
    for (int i = tid; i < 30 * 128; i += 256) sQK[i] = g_QK[b * 3840 + i];
    if (tid < 128) sacc[tid] = 0.f;
    __syncthreads();
    float lacc[4] = {0.f, 0.f, 0.f, 0.f};
    for (int t = ch * 250 + warp; t < ch * 250 + 250; t += 8) {
        const float* sr = g_s1 + (size_t)(b * 2048 + t) * 32;
        float sc = (lane < 30) ? sr[lane] : -1e30f;
        float mx = sc;
        #pragma unroll
        for (int o = 16; o; o >>= 1) mx = fmaxf(mx, __shfl_xor_sync(0xffffffffu, mx, o));
        float e = (lane < 30) ? expf(sc - mx) : 0.f;
        float sm = e;
        #pragma unroll
        for (int o = 16; o; o >>= 1) sm += __shfl_xor_sync(0xffffffffu, sm, o);
        float p = e / sm;
        // s2[kk] for kk = lane*4 .. lane*4+3
        float s0 = 0.f, s1v = 0.f, s2v = 0.f, s3v = 0.f;
        #pragma unroll 6
        for (int w = 0; w < 30; w++) {
            float pw = __shfl_sync(0xffffffffu, p, w);
            const float* qk = sQK + w * 128 + lane * 4;
            s0 += pw * qk[0]; s1v += pw * qk[1]; s2v += pw * qk[2]; s3v += pw * qk[3];
        }
        // group softmax over 16 (= 4 lanes x 4 values); group = lane>>2
        float gm = fmaxf(fmaxf(s0, s1v), fmaxf(s2v, s3v));
        gm = fmaxf(gm, __shfl_xor_sync(0xffffffffu, gm, 1));
        gm = fmaxf(gm, __shfl_xor_sync(0xffffffffu, gm, 2));
        float e0 = expf(s0 - gm), e1 = expf(s1v - gm), e2 = expf(s2v - gm), e3 = expf(s3v - gm);
        float gs = e0 + e1 + e2 + e3;
        gs += __shfl_xor_sync(0xffffffffu, gs, 1);
        gs += __shfl_xor_sync(0xffffffffu, gs, 2);
        float inv = 1.f / gs;
        lacc[0] += e0 * inv; lacc[1] += e1 * inv; lacc[2] += e2 * inv; lacc[3] += e3 * inv;
    }
    #pragma unroll
    for (int j = 0; j < 4; j++) atomicAdd(&sacc[lane * 4 + j], lacc[j]);
    __syncthreads();
    if (tid < 128) {
        int kk = tid;
        int proj = kk >> 6, r = kk & 63;
        int opt = r >> 4, w = r & 15;
        atomicAdd(&g_cm[((opt * 16 + b) * 2 + proj) * 16 + w], sacc[kk]);
    }
}

__global__ void zero_cm_kernel() {
    int i = blockIdx.x * blockDim.x + threadIdx.x;
    if (i < 4 * 16 * 2 * 16) g_cm[i] = 0.f;
}

// ---------------- final MLP ----------------
__global__ void final_kernel(const float* __restrict__ as1W, const float* __restrict__ as1b,
                             const float* __restrict__ as2W, const float* __restrict__ as2b,
                             float* __restrict__ out) {
    __shared__ float sav[600];
    __shared__ float sh[75];
    __shared__ float scm[32];
    int bid = blockIdx.x;
    int opt = bid >> 4, b = bid & 15;
    int ob = opt * 16 + b;
    int tid = threadIdx.x;
    if (tid < 32) scm[tid] = g_cm[ob * 32 + tid] * (1.0f / 2000.0f);
    __syncthreads();
    for (int d = tid; d < 300; d += 128) {
        float a2 = 0.f, a3 = 0.f;
        #pragma unroll
        for (int w = 0; w < 16; w++) {
            float ov = g_optf[(ob * 16 + w) * 300 + d];
            a2 += scm[w] * ov;
            a3 += scm[16 + w] * ov;
        }
        sav[d] = a2;
        sav[300 + d] = a3;
    }
    __syncthreads();
    for (int j = tid; j < 75; j += 128) {
        float a = __ldg(&as1b[j]);
        for (int i2 = 0; i2 < 600; i2++) a += __ldg(&as1W[j * 600 + i2]) * sav[i2];
        sh[j] = fmaxf(a, 0.f);
    }
    __syncthreads();
    if (tid == 0) {
        float s = __ldg(as2b);
        for (int j = 0; j < 75; j++) s += __ldg(&as2W[j]) * sh[j];
        out[b * 4 + opt] = s;
    }
}

// ---------------- launch ----------------
extern "C" void kernel_launch(void* const* d_in, const int* in_sizes, int n_in,
                              void* d_out, int out_size) {
    const int* opt_idx[4] = {(const int*)d_in[0], (const int*)d_in[1],
                             (const int*)d_in[2], (const int*)d_in[3]};
    const int* q_idx = (const int*)d_in[4];
    const int* a_idx = (const int*)d_in[5];
    const float* emb = (const float*)d_in[6];
    const float* ceW = (const float*)d_in[7];
    const float* ceb = (const float*)d_in[8];
    const float* mr1W = (const float*)d_in[9];
    const float* mr1b = (const float*)d_in[10];
    const float* mr2W = (const float*)d_in[11];
    const float* mr2b = (const float*)d_in[12];
    const float* Wz = (const float*)d_in[13];
    const float* bz = (const float*)d_in[14];
    const float* Wo = (const float*)d_in[15];
    const float* bo = (const float*)d_in[16];
    const float* f1W = (const float*)d_in[17];
    const float* f1b = (const float*)d_in[18];
    const float* f2W = (const float*)d_in[19];
    const float* f2b = (const float*)d_in[20];
    const float* f3W = (const float*)d_in[21];
    const float* f3b = (const float*)d_in[22];
    const float* as1W = (const float*)d_in[23];
    const float* as1b = (const float*)d_in[24];
    const float* as2W = (const float*)d_in[25];
    const float* as2b = (const float*)d_in[26];

    // weight splits
    split_w<<<(450000 + 255) / 256, 256>>>(ceW, 0, 450000);
    split_w<<<(90000 + 255) / 256, 256>>>(Wz, 5, 90000);
    split_w<<<(90000 + 255) / 256, 256>>>(Wo, 6, 90000);
    split_w<<<(90000 + 255) / 256, 256>>>(f1W, 7, 90000);
    split_w<<<(90000 + 255) / 256, 256>>>(f2W, 8, 90000);
    split_w<<<(90000 + 255) / 256, 256>>>(f3W, 9, 90000);

    // embedding gathers (+ splits; article split doubles as xs r=1 rows)
    gather_split<<<(32000 * 300 + 255) / 256, 256>>>(a_idx, emb, 0, 0, 32000);
    gather_split<<<(480 * 300 + 255) / 256, 256>>>(q_idx, emb, 1, 0, 480);
    for (int o = 0; o < 4; o++)
        gather_split<<<(256 * 300 + 255) / 256, 256>>>(opt_idx[o], emb, 2, o * 256, 256);

    // ContractExpand group sums (r>=2) + CE GEMM (relu, per-range weights)
    xs_kernel<<<(28672 * 300 + 255) / 256, 256>>>();
    gemm_mma<<<dim3(5, 474), 256>>>(0, 0, ceb, 0, 60672, 1, 1);

    // z, o projections (tanh)
    gemm_mma<<<dim3(5, 250), 256>>>(0, 5, bz, 1, 32000, 2, 0);
    gemm_mma<<<dim3(5, 250), 256>>>(0, 6, bo, 2, 32000, 2, 0);

    // chunked scan (gate fused) -> enc split
    scanA_kernel<<<dim3(40, 16), 300>>>(mr1W, mr1b, mr2W, mr2b);
    scanB_kernel<<<16, 300>>>();
    scanC_kernel<<<dim3(40, 16), 300>>>(mr1W, mr1b, mr2W, mr2b);

    // f1 keys (split, per-batch) then attn1 scores GEMM
    gemm_mma<<<dim3(5, 4), 256>>>(1, 7, f1b, 0, 480, 4, 0);
    gemm_mma<<<dim3(1, 256), 256>>>(3, 0, nullptr, 5, 32768, 3, 2);

    // option keys (fp32) + QK + fused attention-2
    gemm_mma<<<dim3(5, 8), 256>>>(2, 8, f2b, 3, 1024, 0, 0);
    gemm_mma<<<dim3(5, 8), 256>>>(2, 9, f3b, 4, 1024, 0, 0);
    qk_kernel<<<16, 256>>>();
    zero_cm_kernel<<<8, 256>>>();
    attn_fused<<<dim3(8, 16), 256>>>();

    // final MLP
    final_kernel<<<64, 128>>>(as1W, as1b, as2W, as2b, (float*)d_out);
}

// round 6
// speedup vs baseline: 1.4539x; 1.4539x over previous
#include <cuda_runtime.h>
#include <cuda_bf16.h>
#include <math.h>

// DIM=300 (K padded to 304 = 19 k16 stages), B=16, T=2000, Tq=30, Topt=16
#define KP 304
#define NSTAGE 19
// CE padded row layout (128-aligned range starts): 0,32000,48000,56064,59392; M=60672

typedef __nv_bfloat16 bf16;

// ---------------- scratch ----------------
__device__ float g_art[32000 * 300];
__device__ bf16  g_xsh[60672 * KP], g_xsl[60672 * KP];   // rows 0..32000 = article split
__device__ float g_h[60672 * 300];
__device__ float g_z[32000 * 300];
__device__ float g_o[32000 * 300];
__device__ bf16  g_ench[32768 * KP], g_encl[32768 * KP]; // rows b*2048+t (pad rows stay 0)
__device__ float g_s1[32768 * 32];                       // attn1 scores
__device__ bf16  g_qh[512 * KP], g_ql[512 * KP];         // rows b*30+w (f1-keys GEMM A)
__device__ bf16  g_qph[2048 * KP], g_qpl[2048 * KP];     // rows b*128+w1 (QK GEMM A, pads 0)
__device__ float g_optf[1024 * 300];
__device__ bf16  g_opth[1024 * KP], g_optl[1024 * KP];
__device__ bf16  g_kb1h[16 * 64 * KP], g_kb1l[16 * 64 * KP];   // f1 keys per batch (rows 30..63 zero)
__device__ bf16  g_kb2h[16 * 128 * KP], g_kb2l[16 * 128 * KP]; // f2/f3 keys per batch
__device__ float g_QK[16 * 30 * 128];
__device__ float g_scA[16 * 40 * 300], g_scB[16 * 40 * 300], g_scC[16 * 40 * 300];
__device__ float g_cm[4 * 16 * 2 * 16];
// weight slots [320][KP]: 0-4 ce, 5 Wz, 6 Wo, 7 f1, 8 f2, 9 f3
#define WSLOT (320 * KP)
__device__ bf16 g_wh[10 * WSLOT], g_wl[10 * WSLOT];

// ---------------- helpers ----------------
__device__ __forceinline__ void split2(float x, bf16& h, bf16& l) {
    h = __float2bfloat16(x);
    l = __float2bfloat16(x - __bfloat162float(h));
}
__device__ __forceinline__ void cp16(void* s, const void* g) {
    unsigned sa = (unsigned)__cvta_generic_to_shared(s);
    asm volatile("cp.async.cg.shared.global [%0], [%1], 16;" :: "r"(sa), "l"(g));
}
__device__ __forceinline__ void mma16816(float* c, const unsigned* a, const unsigned* b) {
    asm volatile(
        "mma.sync.aligned.m16n8k16.row.col.f32.bf16.bf16.f32 "
        "{%0,%1,%2,%3}, {%4,%5,%6,%7}, {%8,%9}, {%0,%1,%2,%3};\n"
        : "+f"(c[0]), "+f"(c[1]), "+f"(c[2]), "+f"(c[3])
        : "r"(a[0]), "r"(a[1]), "r"(a[2]), "r"(a[3]), "r"(b[0]), "r"(b[1]));
}

// ---------------- weight prep ----------------
__global__ void split_w(const float* __restrict__ src, int slotBase, int count) {
    int i = blockIdx.x * blockDim.x + threadIdx.x;
    if (i >= count) return;
    int slot = slotBase + i / 90000;
    int rem = i % 90000;
    int n = rem / 300, k = rem - n * 300;
    bf16 h, l; split2(src[i], h, l);
    int o = slot * WSLOT + n * KP + k;
    g_wh[o] = h; g_wl[o] = l;
}

// ---------------- embedding gather + split ----------------
__global__ void gather_split(const int* __restrict__ idx, const float* __restrict__ emb,
                             int sel, int rowOff, int nrows) {
    int i = blockIdx.x * blockDim.x + threadIdx.x;
    if (i >= nrows * 300) return;
    int r = i / 300, d = i - r * 300;
    float x = emb[idx[r] * 300 + d];
    int R = rowOff + r;
    bf16 hb, lb; split2(x, hb, lb);
    if (sel == 0) {          // article: fp32 + split straight into xs rows (r=1 block)
        g_art[R * 300 + d] = x;
        g_xsh[R * KP + d] = hb; g_xsl[R * KP + d] = lb;
    } else if (sel == 1) {   // question: compact rows + per-batch padded rows
        g_qh[R * KP + d] = hb; g_ql[R * KP + d] = lb;
        int b = R / 30, w1 = R - b * 30;
        int o = (b * 128 + w1) * KP + d;
        g_qph[o] = hb; g_qpl[o] = lb;
    } else {                 // options
        g_optf[R * 300 + d] = x;
        g_opth[R * KP + d] = hb; g_optl[R * KP + d] = lb;
    }
}

// ---------------- group sums for r>=2 ranges ----------------
__global__ void xs_kernel() {
    int i = blockIdx.x * blockDim.x + threadIdx.x;
    if (i >= 28672 * 300) return;
    int R = 32000 + i / 300, d = i % 300;
    float s;
    if (R < 48000) {
        int L = R - 32000, b = L / 1000, g = L - b * 1000;
        int base = (b * 2000 + g * 2) * 300 + d;
        s = g_art[base] + g_art[base + 300];
    } else if (R < 56000) {
        int L = R - 48000, b = L / 500, g = L - b * 500;
        int base = (b * 2000 + g * 4) * 300 + d;
        s = 0.f;
        #pragma unroll
        for (int j = 0; j < 4; j++) s += g_art[base + j * 300];
    } else if (R < 56064) return;
    else if (R < 59264) {
        int L = R - 56064, b = L / 200, g = L - b * 200;
        int base = (b * 2000 + g * 10) * 300 + d;
        s = 0.f;
        #pragma unroll
        for (int j = 0; j < 10; j++) s += g_art[base + j * 300];
    } else if (R < 59392) return;
    else {
        int L = R - 59392, b = L / 80, g = L - b * 80;
        int base = (b * 2000 + g * 25) * 300 + d;
        s = 0.f;
        #pragma unroll
        for (int j = 0; j < 25; j++) s += g_art[base + j * 300];
    }
    bf16 h, l; split2(s, h, l);
    g_xsh[R * KP + d] = h;
    g_xsl[R * KP + d] = l;
}

// ---------------- tensor-core GEMM ----------------
// C = act(A(M,300) @ W(300,300)^T + bias); bf16 2-split (hh+hl+lh).
// wmode: 0 slot, 1 CE per-range, 2 f1 keys per batch (bm>>11), 3 f2/f3 keys per batch (bm>>7)
// act: 0 none /1 relu /2 tanh (fp32 C stride 300); 3 scores (fp32 stride 32, n<32, no bias);
//      4 f1-key split -> g_kb1; 5 f2/f3-key split -> g_kb2 (proj = wslot-8);
//      6 QK epilogue -> g_QK
#define SAST 24
__global__ void __launch_bounds__(256) gemm_mma(int Asel, int wslot, const float* __restrict__ bias,
                                                int Csel, int M, int act, int wmode) {
    __shared__ __align__(16) bf16 sA[2][2][128 * SAST];
    __shared__ __align__(16) bf16 sB[2][2][64 * SAST];

    const bf16 *Ah, *Al;
    switch (Asel) {
        case 0: Ah = g_xsh;  Al = g_xsl;  break;
        case 1: Ah = g_qh;   Al = g_ql;   break;
        case 2: Ah = g_opth; Al = g_optl; break;
        case 4: Ah = g_qph;  Al = g_qpl;  break;
        default: Ah = g_ench; Al = g_encl; break;
    }
    float* C;
    switch (Csel) {
        case 0: C = g_h;  break;
        case 1: C = g_z;  break;
        case 2: C = g_o;  break;
        default: C = g_s1; break;
    }
    int bm = blockIdx.y * 128, bn = blockIdx.x * 64;
    const bf16 *Wh, *Wl;
    if (wmode == 1) {
        int slot = (bm < 32000) ? 0 : (bm < 48000) ? 1 : (bm < 56064) ? 2 : (bm < 59392) ? 3 : 4;
        bias += slot * 300;
        Wh = g_wh + slot * WSLOT; Wl = g_wl + slot * WSLOT;
    } else if (wmode == 2) {
        int b = bm >> 11;
        Wh = g_kb1h + b * 64 * KP; Wl = g_kb1l + b * 64 * KP;
    } else if (wmode == 3) {
        int b = bm >> 7;
        Wh = g_kb2h + b * 128 * KP; Wl = g_kb2l + b * 128 * KP;
    } else {
        Wh = g_wh + wslot * WSLOT; Wl = g_wl + wslot * WSLOT;
    }

    int tid = threadIdx.x;
    int lane = tid & 31, warp = tid >> 5;
    int wm = warp & 3, wn = warp >> 2;

    auto issue = [&](int s, int buf) {
        int kt = s * 16;
        int row = tid >> 1, kh = (tid & 1) * 8;
        cp16(&sA[buf][0][row * SAST + kh], Ah + (size_t)(bm + row) * KP + kt + kh);
        cp16(&sA[buf][1][row * SAST + kh], Al + (size_t)(bm + row) * KP + kt + kh);
        if (tid < 128) {
            int br = tid >> 1, bkh = (tid & 1) * 8;
            cp16(&sB[buf][0][br * SAST + bkh], Wh + (size_t)(bn + br) * KP + kt + bkh);
        } else {
            int t = tid - 128;
            int br = t >> 1, bkh = (t & 1) * 8;
            cp16(&sB[buf][1][br * SAST + bkh], Wl + (size_t)(bn + br) * KP + kt + bkh);
        }
        asm volatile("cp.async.commit_group;");
    };

    float acc[2][4][4];
    #pragma unroll
    for (int mi = 0; mi < 2; mi++)
        #pragma unroll
        for (int ni = 0; ni < 4; ni++)
            #pragma unroll
            for (int j = 0; j < 4; j++) acc[mi][ni][j] = 0.f;

    issue(0, 0);
    issue(1, 1);
    asm volatile("cp.async.wait_group 1;");
    __syncthreads();

    int r0 = wm * 32 + (lane >> 2);
    int kc = lane & 3;
    int nb0 = wn * 32 + (lane >> 2);

    for (int s = 0; s < NSTAGE; s++) {
        int buf = s & 1;
        const unsigned* A32h = (const unsigned*)sA[buf][0];
        const unsigned* A32l = (const unsigned*)sA[buf][1];
        const unsigned* B32h = (const unsigned*)sB[buf][0];
        const unsigned* B32l = (const unsigned*)sB[buf][1];
        unsigned ah[2][4], al[2][4], bh[4][2], bl[4][2];
        #pragma unroll
        for (int mi = 0; mi < 2; mi++) {
            int r = r0 + mi * 16;
            int i0 = r * (SAST / 2) + kc;
            int i1 = (r + 8) * (SAST / 2) + kc;
            ah[mi][0] = A32h[i0];     ah[mi][1] = A32h[i1];
            ah[mi][2] = A32h[i0 + 4]; ah[mi][3] = A32h[i1 + 4];
            al[mi][0] = A32l[i0];     al[mi][1] = A32l[i1];
            al[mi][2] = A32l[i0 + 4]; al[mi][3] = A32l[i1 + 4];
        }
        #pragma unroll
        for (int ni = 0; ni < 4; ni++) {
            int n = nb0 + ni * 8;
            int i0 = n * (SAST / 2) + kc;
            bh[ni][0] = B32h[i0]; bh[ni][1] = B32h[i0 + 4];
            bl[ni][0] = B32l[i0]; bl[ni][1] = B32l[i0 + 4];
        }
        #pragma unroll
        for (int mi = 0; mi < 2; mi++)
            #pragma unroll
            for (int ni = 0; ni < 4; ni++) {
                mma16816(acc[mi][ni], ah[mi], bh[ni]);
                mma16816(acc[mi][ni], ah[mi], bl[ni]);
                mma16816(acc[mi][ni], al[mi], bh[ni]);
            }
        __syncthreads();
        if (s + 2 < NSTAGE) {
            issue(s + 2, buf);
            asm volatile("cp.async.wait_group 1;");
        } else {
            asm volatile("cp.async.wait_group 0;");
        }
        __syncthreads();
    }

    // epilogue
    #pragma unroll
    for (int mi = 0; mi < 2; mi++) {
        int mrow = bm + wm * 32 + mi * 16 + (lane >> 2);
        #pragma unroll
        for (int ni = 0; ni < 4; ni++) {
            int ncol = bn + wn * 32 + ni * 8 + 2 * (lane & 3);
            #pragma unroll
            for (int rr = 0; rr < 2; rr++) {
                int m = mrow + rr * 8;
                #pragma unroll
                for (int cc = 0; cc < 2; cc++) {
                    int n = ncol + cc;
                    float v = acc[mi][ni][rr * 2 + cc];
                    if (act == 3) {
                        if (m < M && n < 32) C[(size_t)m * 32 + n] = v;
                    } else if (act == 4) {
                        if (m < 480 && n < 300) {
                            v += __ldg(&bias[n]);
                            int b = m / 30, w = m - b * 30;
                            bf16 hb, lb; split2(v, hb, lb);
                            int o = (b * 64 + w) * KP + n;
                            g_kb1h[o] = hb; g_kb1l[o] = lb;
                        }
                    } else if (act == 5) {
                        if (m < 1024 && n < 300) {
                            v += __ldg(&bias[n]);
                            // m = (opt*16 + b)*16 + w ; kk = proj*64 + opt*16 + w, proj = wslot-8
                            int b = (m >> 4) & 15, opt = m >> 8, w = m & 15;
                            int kk = (wslot - 8) * 64 + opt * 16 + w;
                            bf16 hb, lb; split2(v, hb, lb);
                            int o = (b * 128 + kk) * KP + n;
                            g_kb2h[o] = hb; g_kb2l[o] = lb;
                        }
                    } else if (act == 6) {
                        int w1 = m & 127;
                        if (m < 2048 && w1 < 30 && n < 128)
                            g_QK[(m >> 7) * 3840 + w1 * 128 + n] = v;
                    } else {
                        if (m < M && n < 300) {
                            v += __ldg(&bias[n]);
                            if (act == 1) v = fmaxf(v, 0.f);
                            else if (act == 2) v = tanhf(v);
                            C[(size_t)m * 300 + n] = v;
                        }
                    }
                }
            }
        }
    }
}

// ---------------- fused gate evaluation ----------------
__device__ __forceinline__ float gate_val(int b, int t, int d, const float* m1,
                                          const float* mb1, const float* m2, float mb2) {
    float y0 = g_h[(b * 2000 + t) * 300 + d];
    float y1 = g_h[(32000 + b * 1000 + (t >> 1)) * 300 + d] * 0.5f;
    float y2 = g_h[(48000 + b * 500 + (t >> 2)) * 300 + d] * 0.25f;
    float y3 = g_h[(56064 + b * 200 + t / 10) * 300 + d] * (1.0f / 10.0f);
    float y4 = g_h[(59392 + b * 80 + t / 25) * 300 + d] * (1.0f / 25.0f);
    float acc = mb2;
    #pragma unroll
    for (int k = 0; k < 3; k++) {
        float hk = mb1[k] + m1[k * 5] * y0 + m1[k * 5 + 1] * y1 + m1[k * 5 + 2] * y2
                 + m1[k * 5 + 3] * y3 + m1[k * 5 + 4] * y4;
        acc += m2[k] * fmaxf(hk, 0.f);
    }
    return fmaxf(acc, 0.f);
}

// ---------------- chunked linear scan (gate fused) ----------------
__global__ void scanA_kernel(const float* __restrict__ mr1W, const float* __restrict__ mr1b,
                             const float* __restrict__ mr2W, const float* __restrict__ mr2b) {
    int ch = blockIdx.x, b = blockIdx.y, d = threadIdx.x;
    float m1[15], mb1[3], m2[3];
    #pragma unroll
    for (int k = 0; k < 15; k++) m1[k] = __ldg(&mr1W[k]);
    #pragma unroll
    for (int k = 0; k < 3; k++) { mb1[k] = __ldg(&mr1b[k]); m2[k] = __ldg(&mr2W[k]); }
    float mb2 = __ldg(mr2b);
    int t0 = ch * 50;
    float a = 1.f, bb = 0.f;
    for (int j = 0; j < 50; j++) {
        float g = gate_val(b, t0 + j, d, m1, mb1, m2, mb2);
        float z = g_z[(b * 2000 + t0 + j) * 300 + d];
        a *= g;
        bb = g * (bb - z) + z;
    }
    int o = (b * 40 + ch) * 300 + d;
    g_scA[o] = a;
    g_scB[o] = bb;
}
__global__ void scanB_kernel() {
    int b = blockIdx.x, d = threadIdx.x;
    float c = 0.f;
    for (int ch = 0; ch < 40; ch++) {
        int o = (b * 40 + ch) * 300 + d;
        g_scC[o] = c;
        c = g_scA[o] * c + g_scB[o];
    }
}
__global__ void scanC_kernel(const float* __restrict__ mr1W, const float* __restrict__ mr1b,
                             const float* __restrict__ mr2W, const float* __restrict__ mr2b) {
    int ch = blockIdx.x, b = blockIdx.y, d = threadIdx.x;
    float m1[15], mb1[3], m2[3];
    #pragma unroll
    for (int k = 0; k < 15; k++) m1[k] = __ldg(&mr1W[k]);
    #pragma unroll
    for (int k = 0; k < 3; k++) { mb1[k] = __ldg(&mr1b[k]); m2[k] = __ldg(&mr2W[k]); }
    float mb2 = __ldg(mr2b);
    float c = g_scC[(b * 40 + ch) * 300 + d];
    int t0 = ch * 50;
    for (int j = 0; j < 50; j++) {
        int t = t0 + j;
        float g = gate_val(b, t, d, m1, mb1, m2, mb2);
        float z = g_z[(b * 2000 + t) * 300 + d];
        c = g * (c - z) + z;
        float enc = g_o[(b * 2000 + t) * 300 + d] * c;
        bf16 hb, lb; split2(enc, hb, lb);
        int o = (b * 2048 + t) * KP + d;
        g_ench[o] = hb; g_encl[o] = lb;
    }
}

// ---------------- fused: softmax30 -> P.QK -> group softmax16 -> column sums ----------------
__global__ void attn_fused() {
    __shared__ float sQK[30 * 128];
    __shared__ float sacc[128];
    int ch = blockIdx.x, b = blockIdx.y;
    int tid = threadIdx.x, warp = tid >> 5, lane = tid & 31;
    for (int i = tid; i < 30 * 128; i += 256) sQK[i] = g_QK[b * 3840 + i];
    if (tid < 128) sacc[tid] = 0.f;
    __syncthreads();
    float lacc[4] = {0.f, 0.f, 0.f, 0.f};
    for (int t = ch * 250 + warp; t < ch * 250 + 250; t += 8) {
        const float* sr = g_s1 + (size_t)(b * 2048 + t) * 32;
        float sc = (lane < 30) ? sr[lane] : -1e30f;
        float mx = sc;
        #pragma unroll
        for (int o = 16; o; o >>= 1) mx = fmaxf(mx, __shfl_xor_sync(0xffffffffu, mx, o));
        float e = (lane < 30) ? expf(sc - mx) : 0.f;
        float sm = e;
        #pragma unroll
        for (int o = 16; o; o >>= 1) sm += __shfl_xor_sync(0xffffffffu, sm, o);
        float p = e / sm;
        float s0 = 0.f, s1v = 0.f, s2v = 0.f, s3v = 0.f;
        #pragma unroll 6
        for (int w = 0; w < 30; w++) {
            float pw = __shfl_sync(0xffffffffu, p, w);
            const float* qk = sQK + w * 128 + lane * 4;
            s0 += pw * qk[0]; s1v += pw * qk[1]; s2v += pw * qk[2]; s3v += pw * qk[3];
        }
        float gm = fmaxf(fmaxf(s0, s1v), fmaxf(s2v, s3v));
        gm = fmaxf(gm, __shfl_xor_sync(0xffffffffu, gm, 1));
        gm = fmaxf(gm, __shfl_xor_sync(0xffffffffu, gm, 2));
        float e0 = expf(s0 - gm), e1 = expf(s1v - gm), e2 = expf(s2v - gm), e3 = expf(s3v - gm);
        float gs = e0 + e1 + e2 + e3;
        gs += __shfl_xor_sync(0xffffffffu, gs, 1);
        gs += __shfl_xor_sync(0xffffffffu, gs, 2);
        float inv = 1.f / gs;
        lacc[0] += e0 * inv; lacc[1] += e1 * inv; lacc[2] += e2 * inv; lacc[3] += e3 * inv;
    }
    #pragma unroll
    for (int j = 0; j < 4; j++) atomicAdd(&sacc[lane * 4 + j], lacc[j]);
    __syncthreads();
    if (tid < 128) {
        int kk = tid;
        int proj = kk >> 6, r = kk & 63;
        int opt = r >> 4, w = r & 15;
        atomicAdd(&g_cm[((opt * 16 + b) * 2 + proj) * 16 + w], sacc[kk]);
    }
}

__global__ void zero_cm_kernel() {
    int i = blockIdx.x * blockDim.x + threadIdx.x;
    if (i < 4 * 16 * 2 * 16) g_cm[i] = 0.f;
}

// ---------------- final MLP ----------------
__global__ void final_kernel(const float* __restrict__ as1W, const float* __restrict__ as1b,
                             const float* __restrict__ as2W, const float* __restrict__ as2b,
                             float* __restrict__ out) {
    __shared__ float sav[600];
    __shared__ float sh[75];
    __shared__ float scm[32];
    int bid = blockIdx.x;
    int opt = bid >> 4, b = bid & 15;
    int ob = opt * 16 + b;
    int tid = threadIdx.x;
    if (tid < 32) scm[tid] = g_cm[ob * 32 + tid] * (1.0f / 2000.0f);
    __syncthreads();
    for (int d = tid; d < 300; d += 128) {
        float a2 = 0.f, a3 = 0.f;
        #pragma unroll
        for (int w = 0; w < 16; w++) {
            float ov = g_optf[(ob * 16 + w) * 300 + d];
            a2 += scm[w] * ov;
            a3 += scm[16 + w] * ov;
        }
        sav[d] = a2;
        sav[300 + d] = a3;
    }
    __syncthreads();
    for (int j = tid; j < 75; j += 128) {
        float a = __ldg(&as1b[j]);
        for (int i2 = 0; i2 < 600; i2++) a += __ldg(&as1W[j * 600 + i2]) * sav[i2];
        sh[j] = fmaxf(a, 0.f);
    }
    __syncthreads();
    if (tid == 0) {
        float s = __ldg(as2b);
        for (int j = 0; j < 75; j++) s += __ldg(&as2W[j]) * sh[j];
        out[b * 4 + opt] = s;
    }
}

// ---------------- launch ----------------
extern "C" void kernel_launch(void* const* d_in, const int* in_sizes, int n_in,
                              void* d_out, int out_size) {
    const int* opt_idx[4] = {(const int*)d_in[0], (const int*)d_in[1],
                             (const int*)d_in[2], (const int*)d_in[3]};
    const int* q_idx = (const int*)d_in[4];
    const int* a_idx = (const int*)d_in[5];
    const float* emb = (const float*)d_in[6];
    const float* ceW = (const float*)d_in[7];
    const float* ceb = (const float*)d_in[8];
    const float* mr1W = (const float*)d_in[9];
    const float* mr1b = (const float*)d_in[10];
    const float* mr2W = (const float*)d_in[11];
    const float* mr2b = (const float*)d_in[12];
    const float* Wz = (const float*)d_in[13];
    const float* bz = (const float*)d_in[14];
    const float* Wo = (const float*)d_in[15];
    const float* bo = (const float*)d_in[16];
    const float* f1W = (const float*)d_in[17];
    const float* f1b = (const float*)d_in[18];
    const float* f2W = (const float*)d_in[19];
    const float* f2b = (const float*)d_in[20];
    const float* f3W = (const float*)d_in[21];
    const float* f3b = (const float*)d_in[22];
    const float* as1W = (const float*)d_in[23];
    const float* as1b = (const float*)d_in[24];
    const float* as2W = (const float*)d_in[25];
    const float* as2b = (const float*)d_in[26];

    // Launches 1-5, then the CE GEMM as launch #6 so ncu (-s 5 -c 1) profiles it.
    split_w<<<(450000 + 255) / 256, 256>>>(ceW, 0, 450000);                    // 1
    gather_split<<<(32000 * 300 + 255) / 256, 256>>>(a_idx, emb, 0, 0, 32000); // 2
    xs_kernel<<<(28672 * 300 + 255) / 256, 256>>>();                           // 3
    split_w<<<(90000 + 255) / 256, 256>>>(Wz, 5, 90000);                       // 4
    split_w<<<(90000 + 255) / 256, 256>>>(Wo, 6, 90000);                       // 5
    gemm_mma<<<dim3(5, 474), 256>>>(0, 0, ceb, 0, 60672, 1, 1);                // 6 <- profiled

    split_w<<<(90000 + 255) / 256, 256>>>(f1W, 7, 90000);
    split_w<<<(90000 + 255) / 256, 256>>>(f2W, 8, 90000);
    split_w<<<(90000 + 255) / 256, 256>>>(f3W, 9, 90000);
    gather_split<<<(480 * 300 + 255) / 256, 256>>>(q_idx, emb, 1, 0, 480);
    for (int o = 0; o < 4; o++)
        gather_split<<<(256 * 300 + 255) / 256, 256>>>(opt_idx[o], emb, 2, o * 256, 256);

    // z, o projections (tanh)
    gemm_mma<<<dim3(5, 250), 256>>>(0, 5, bz, 1, 32000, 2, 0);
    gemm_mma<<<dim3(5, 250), 256>>>(0, 6, bo, 2, 32000, 2, 0);

    // chunked scan (gate fused) -> enc split
    scanA_kernel<<<dim3(40, 16), 300>>>(mr1W, mr1b, mr2W, mr2b);
    scanB_kernel<<<16, 300>>>();
    scanC_kernel<<<dim3(40, 16), 300>>>(mr1W, mr1b, mr2W, mr2b);

    // f1 keys (split, per-batch) then attn1 scores GEMM
    gemm_mma<<<dim3(5, 4), 256>>>(1, 7, f1b, 0, 480, 4, 0);
    gemm_mma<<<dim3(1, 256), 256>>>(3, 0, nullptr, 5, 32768, 3, 2);

    // option keys (split, per-batch) + QK GEMM + fused attention-2
    gemm_mma<<<dim3(5, 8), 256>>>(2, 8, f2b, 0, 1024, 5, 0);
    gemm_mma<<<dim3(5, 8), 256>>>(2, 9, f3b, 1, 1024, 5, 0);
    gemm_mma<<<dim3(2, 16), 256>>>(4, 0, nullptr, 5, 2048, 6, 3);
    zero_cm_kernel<<<8, 256>>>();
    attn_fused<<<dim3(8, 16), 256>>>();

    // final MLP
    final_kernel<<<64, 128>>>(as1W, as1b, as2W, as2b, (float*)d_out);
}

// round 7
// speedup vs baseline: 1.4614x; 1.0052x over previous
#include <cuda_runtime.h>
#include <cuda_bf16.h>
#include <math.h>

// DIM=300 (K padded to 304 = 19 k16 stages), B=16, T=2000, Tq=30, Topt=16
#define KP 304
#define NSTAGE 19
// CE padded row layout (128-aligned range starts): 0,32000,48000,56064,59392; M=60672

typedef __nv_bfloat16 bf16;

// ---------------- scratch ----------------
__device__ float g_art[32000 * 300];
__device__ bf16  g_xsh[60672 * KP], g_xsl[60672 * KP];   // rows 0..32000 = article split
__device__ float g_h[60672 * 300];
__device__ float g_z[32000 * 300];
__device__ float g_o[32000 * 300];
__device__ bf16  g_ench[32768 * KP], g_encl[32768 * KP]; // rows b*2048+t (pad rows stay 0)
__device__ float g_s1[32768 * 32];                       // attn1 scores
__device__ bf16  g_qh[512 * KP], g_ql[512 * KP];         // rows b*30+w (f1-keys GEMM A)
__device__ bf16  g_qph[2048 * KP], g_qpl[2048 * KP];     // rows b*128+w1 (QK GEMM A, pads 0)
__device__ float g_optf[1024 * 300];
__device__ bf16  g_opth[1024 * KP], g_optl[1024 * KP];
__device__ bf16  g_kb1h[16 * 64 * KP], g_kb1l[16 * 64 * KP];   // f1 keys per batch (rows 30..63 zero)
__device__ bf16  g_kb2h[16 * 128 * KP], g_kb2l[16 * 128 * KP]; // f2/f3 keys per batch
__device__ float g_QK[16 * 30 * 128];
__device__ float g_scA[16 * 40 * 300], g_scB[16 * 40 * 300], g_scC[16 * 40 * 300];
__device__ float g_cm[4 * 16 * 2 * 16];
// weight slots [320][KP]: 0-4 ce, 5 Wz, 6 Wo, 7 f1, 8 f2, 9 f3
#define WSLOT (320 * KP)
__device__ bf16 g_wh[10 * WSLOT], g_wl[10 * WSLOT];

// ---------------- helpers ----------------
__device__ __forceinline__ void split2(float x, bf16& h, bf16& l) {
    h = __float2bfloat16(x);
    l = __float2bfloat16(x - __bfloat162float(h));
}
__device__ __forceinline__ void cp16(void* s, const void* g) {
    unsigned sa = (unsigned)__cvta_generic_to_shared(s);
    asm volatile("cp.async.cg.shared.global [%0], [%1], 16;" :: "r"(sa), "l"(g));
}
__device__ __forceinline__ void mma16816(float* c, const unsigned* a, const unsigned* b) {
    asm volatile(
        "mma.sync.aligned.m16n8k16.row.col.f32.bf16.bf16.f32 "
        "{%0,%1,%2,%3}, {%4,%5,%6,%7}, {%8,%9}, {%0,%1,%2,%3};\n"
        : "+f"(c[0]), "+f"(c[1]), "+f"(c[2]), "+f"(c[3])
        : "r"(a[0]), "r"(a[1]), "r"(a[2]), "r"(a[3]), "r"(b[0]), "r"(b[1]));
}
__device__ __forceinline__ void ldsm4(unsigned& r0, unsigned& r1, unsigned& r2, unsigned& r3,
                                      unsigned addr) {
    asm volatile("ldmatrix.sync.aligned.m8n8.x4.shared.b16 {%0,%1,%2,%3}, [%4];"
                 : "=r"(r0), "=r"(r1), "=r"(r2), "=r"(r3) : "r"(addr));
}

// ---------------- weight prep ----------------
__global__ void split_w(const float* __restrict__ src, int slotBase, int count) {
    int i = blockIdx.x * blockDim.x + threadIdx.x;
    if (i >= count) return;
    int slot = slotBase + i / 90000;
    int rem = i % 90000;
    int n = rem / 300, k = rem - n * 300;
    bf16 h, l; split2(src[i], h, l);
    int o = slot * WSLOT + n * KP + k;
    g_wh[o] = h; g_wl[o] = l;
}

// ---------------- embedding gather + split ----------------
__global__ void gather_split(const int* __restrict__ idx, const float* __restrict__ emb,
                             int sel, int rowOff, int nrows) {
    int i = blockIdx.x * blockDim.x + threadIdx.x;
    if (i >= nrows * 300) return;
    int r = i / 300, d = i - r * 300;
    float x = emb[idx[r] * 300 + d];
    int R = rowOff + r;
    bf16 hb, lb; split2(x, hb, lb);
    if (sel == 0) {          // article: fp32 + split straight into xs rows (r=1 block)
        g_art[R * 300 + d] = x;
        g_xsh[R * KP + d] = hb; g_xsl[R * KP + d] = lb;
    } else if (sel == 1) {   // question: compact rows + per-batch padded rows
        g_qh[R * KP + d] = hb; g_ql[R * KP + d] = lb;
        int b = R / 30, w1 = R - b * 30;
        int o = (b * 128 + w1) * KP + d;
        g_qph[o] = hb; g_qpl[o] = lb;
    } else {                 // options
        g_optf[R * 300 + d] = x;
        g_opth[R * KP + d] = hb; g_optl[R * KP + d] = lb;
    }
}

// ---------------- group sums for r>=2 ranges ----------------
__global__ void xs_kernel() {
    int i = blockIdx.x * blockDim.x + threadIdx.x;
    if (i >= 28672 * 300) return;
    int R = 32000 + i / 300, d = i % 300;
    float s;
    if (R < 48000) {
        int L = R - 32000, b = L / 1000, g = L - b * 1000;
        int base = (b * 2000 + g * 2) * 300 + d;
        s = g_art[base] + g_art[base + 300];
    } else if (R < 56000) {
        int L = R - 48000, b = L / 500, g = L - b * 500;
        int base = (b * 2000 + g * 4) * 300 + d;
        s = 0.f;
        #pragma unroll
        for (int j = 0; j < 4; j++) s += g_art[base + j * 300];
    } else if (R < 56064) return;
    else if (R < 59264) {
        int L = R - 56064, b = L / 200, g = L - b * 200;
        int base = (b * 2000 + g * 10) * 300 + d;
        s = 0.f;
        #pragma unroll
        for (int j = 0; j < 10; j++) s += g_art[base + j * 300];
    } else if (R < 59392) return;
    else {
        int L = R - 59392, b = L / 80, g = L - b * 80;
        int base = (b * 2000 + g * 25) * 300 + d;
        s = 0.f;
        #pragma unroll
        for (int j = 0; j < 25; j++) s += g_art[base + j * 300];
    }
    bf16 h, l; split2(s, h, l);
    g_xsh[R * KP + d] = h;
    g_xsl[R * KP + d] = l;
}

// ---------------- tensor-core GEMM ----------------
// C = act(A(M,300) @ W(300,300)^T + bias); bf16 2-split (hh+hl+lh).
// 3-stage cp.async pipeline, ldmatrix fragment loads, one __syncthreads per stage.
// wmode: 0 slot, 1 CE per-range, 2 f1 keys per batch (bm>>11), 3 f2/f3 keys per batch (bm>>7)
// act: 0 none /1 relu /2 tanh (fp32 C stride 300); 3 scores (fp32 stride 32, n<32, no bias);
//      4 f1-key split -> g_kb1; 5 f2/f3-key split -> g_kb2 (proj = wslot-8);
//      6 QK epilogue -> g_QK
#define SAST 24
// per-buffer element layout (bf16): A h [128*SAST] | A l [128*SAST] | B h [64*SAST] | B l [64*SAST]
#define APL (128 * SAST)                  // 3072
#define BPL (64 * SAST)                   // 1536
#define STG (2 * APL + 2 * BPL)           // 9216 elems = 18432 B
#define GEMM_SMEM (3 * STG * 2)           // 55296 B

__global__ void __launch_bounds__(256) gemm_mma(int Asel, int wslot, const float* __restrict__ bias,
                                                int Csel, int M, int act, int wmode) {
    extern __shared__ __align__(16) bf16 sdy[];

    const bf16 *Ah, *Al;
    switch (Asel) {
        case 0: Ah = g_xsh;  Al = g_xsl;  break;
        case 1: Ah = g_qh;   Al = g_ql;   break;
        case 2: Ah = g_opth; Al = g_optl; break;
        case 4: Ah = g_qph;  Al = g_qpl;  break;
        default: Ah = g_ench; Al = g_encl; break;
    }
    float* C;
    switch (Csel) {
        case 0: C = g_h;  break;
        case 1: C = g_z;  break;
        case 2: C = g_o;  break;
        default: C = g_s1; break;
    }
    int bm = blockIdx.y * 128, bn = blockIdx.x * 64;
    const bf16 *Wh, *Wl;
    if (wmode == 1) {
        int slot = (bm < 32000) ? 0 : (bm < 48000) ? 1 : (bm < 56064) ? 2 : (bm < 59392) ? 3 : 4;
        bias += slot * 300;
        Wh = g_wh + slot * WSLOT; Wl = g_wl + slot * WSLOT;
    } else if (wmode == 2) {
        int b = bm >> 11;
        Wh = g_kb1h + b * 64 * KP; Wl = g_kb1l + b * 64 * KP;
    } else if (wmode == 3) {
        int b = bm >> 7;
        Wh = g_kb2h + b * 128 * KP; Wl = g_kb2l + b * 128 * KP;
    } else {
        Wh = g_wh + wslot * WSLOT; Wl = g_wl + wslot * WSLOT;
    }

    int tid = threadIdx.x;
    int lane = tid & 31, warp = tid >> 5;
    int wm = warp & 3, wn = warp >> 2;

    // issue one k16 stage into buffer buf
    auto issue = [&](int s, int buf) {
        int kt = s * 16;
        bf16* base = sdy + buf * STG;
        int row = tid >> 1, kh = (tid & 1) * 8;
        cp16(base + row * SAST + kh, Ah + (size_t)(bm + row) * KP + kt + kh);
        cp16(base + APL + row * SAST + kh, Al + (size_t)(bm + row) * KP + kt + kh);
        if (tid < 128) {
            int br = tid >> 1, bkh = (tid & 1) * 8;
            cp16(base + 2 * APL + br * SAST + bkh, Wh + (size_t)(bn + br) * KP + kt + bkh);
        } else {
            int t = tid - 128;
            int br = t >> 1, bkh = (t & 1) * 8;
            cp16(base + 2 * APL + BPL + br * SAST + bkh, Wl + (size_t)(bn + br) * KP + kt + bkh);
        }
        asm volatile("cp.async.commit_group;");
    };

    float acc[2][4][4];
    #pragma unroll
    for (int mi = 0; mi < 2; mi++)
        #pragma unroll
        for (int ni = 0; ni < 4; ni++)
            #pragma unroll
            for (int j = 0; j < 4; j++) acc[mi][ni][j] = 0.f;

    // ldmatrix lane-invariant offsets (bf16 elements, within a buffer)
    unsigned sbase = (unsigned)__cvta_generic_to_shared(sdy);
    unsigned aInv0 = (unsigned)((wm * 32 + (lane & 15)) * SAST + (lane >> 4) * 8);
    unsigned aInv1 = aInv0 + 16 * SAST;
    unsigned bInv0 = (unsigned)(2 * APL +
                     (wn * 32 + ((lane >> 4) & 1) * 8 + (lane & 7)) * SAST + ((lane >> 3) & 1) * 8);
    unsigned bInv1 = bInv0 + 16 * SAST;

    issue(0, 0);
    issue(1, 1);

    for (int s = 0; s < NSTAGE; s++) {
        if (s < NSTAGE - 1) asm volatile("cp.async.wait_group 1;");
        else                asm volatile("cp.async.wait_group 0;");
        __syncthreads();
        int buf = s % 3;
        unsigned bb = (unsigned)(buf * STG);
        unsigned ah[2][4], al[2][4], bh[4][2], bl[4][2];
        ldsm4(ah[0][0], ah[0][1], ah[0][2], ah[0][3], sbase + (bb + aInv0) * 2);
        ldsm4(ah[1][0], ah[1][1], ah[1][2], ah[1][3], sbase + (bb + aInv1) * 2);
        ldsm4(al[0][0], al[0][1], al[0][2], al[0][3], sbase + (bb + APL + aInv0) * 2);
        ldsm4(al[1][0], al[1][1], al[1][2], al[1][3], sbase + (bb + APL + aInv1) * 2);
        ldsm4(bh[0][0], bh[0][1], bh[1][0], bh[1][1], sbase + (bb + bInv0) * 2);
        ldsm4(bh[2][0], bh[2][1], bh[3][0], bh[3][1], sbase + (bb + bInv1) * 2);
        ldsm4(bl[0][0], bl[0][1], bl[1][0], bl[1][1], sbase + (bb + BPL + bInv0) * 2);
        ldsm4(bl[2][0], bl[2][1], bl[3][0], bl[3][1], sbase + (bb + BPL + bInv1) * 2);
        #pragma unroll
        for (int mi = 0; mi < 2; mi++)
            #pragma unroll
            for (int ni = 0; ni < 4; ni++) {
                mma16816(acc[mi][ni], ah[mi], bh[ni]);
                mma16816(acc[mi][ni], ah[mi], bl[ni]);
                mma16816(acc[mi][ni], al[mi], bh[ni]);
            }
        if (s + 2 < NSTAGE) issue(s + 2, (s + 2) % 3);
    }

    // epilogue
    #pragma unroll
    for (int mi = 0; mi < 2; mi++) {
        int mrow = bm + wm * 32 + mi * 16 + (lane >> 2);
        #pragma unroll
        for (int ni = 0; ni < 4; ni++) {
            int ncol = bn + wn * 32 + ni * 8 + 2 * (lane & 3);
            #pragma unroll
            for (int rr = 0; rr < 2; rr++) {
                int m = mrow + rr * 8;
                #pragma unroll
                for (int cc = 0; cc < 2; cc++) {
                    int n = ncol + cc;
                    float v = acc[mi][ni][rr * 2 + cc];
                    if (act == 3) {
                        if (m < M && n < 32) C[(size_t)m * 32 + n] = v;
                    } else if (act == 4) {
                        if (m < 480 && n < 300) {
                            v += __ldg(&bias[n]);
                            int b = m / 30, w = m - b * 30;
                            bf16 hb, lb; split2(v, hb, lb);
                            int o = (b * 64 + w) * KP + n;
                            g_kb1h[o] = hb; g_kb1l[o] = lb;
                        }
                    } else if (act == 5) {
                        if (m < 1024 && n < 300) {
                            v += __ldg(&bias[n]);
                            // m = (opt*16 + b)*16 + w ; kk = proj*64 + opt*16 + w, proj = wslot-8
                            int b = (m >> 4) & 15, opt = m >> 8, w = m & 15;
                            int kk = (wslot - 8) * 64 + opt * 16 + w;
                            bf16 hb, lb; split2(v, hb, lb);
                            int o = (b * 128 + kk) * KP + n;
                            g_kb2h[o] = hb; g_kb2l[o] = lb;
                        }
                    } else if (act == 6) {
                        int w1 = m & 127;
                        if (m < 2048 && w1 < 30 && n < 128)
                            g_QK[(m >> 7) * 3840 + w1 * 128 + n] = v;
                    } else {
                        if (m < M && n < 300) {
                            v += __ldg(&bias[n]);
                            if (act == 1) v = fmaxf(v, 0.f);
                            else if (act == 2) v = tanhf(v);
                            C[(size_t)m * 300 + n] = v;
                        }
                    }
                }
            }
        }
    }
}

// ---------------- fused gate evaluation ----------------
__device__ __forceinline__ float gate_val(int b, int t, int d, const float* m1,
                                          const float* mb1, const float* m2, float mb2) {
    float y0 = g_h[(b * 2000 + t) * 300 + d];
    float y1 = g_h[(32000 + b * 1000 + (t >> 1)) * 300 + d] * 0.5f;
    float y2 = g_h[(48000 + b * 500 + (t >> 2)) * 300 + d] * 0.25f;
    float y3 = g_h[(56064 + b * 200 + t / 10) * 300 + d] * (1.0f / 10.0f);
    float y4 = g_h[(59392 + b * 80 + t / 25) * 300 + d] * (1.0f / 25.0f);
    float acc = mb2;
    #pragma unroll
    for (int k = 0; k < 3; k++) {
        float hk = mb1[k] + m1[k * 5] * y0 + m1[k * 5 + 1] * y1 + m1[k * 5 + 2] * y2
                 + m1[k * 5 + 3] * y3 + m1[k * 5 + 4] * y4;
        acc += m2[k] * fmaxf(hk, 0.f);
    }
    return fmaxf(acc, 0.f);
}

// ---------------- chunked linear scan (gate fused) ----------------
__global__ void scanA_kernel(const float* __restrict__ mr1W, const float* __restrict__ mr1b,
                             const float* __restrict__ mr2W, const float* __restrict__ mr2b) {
    int ch = blockIdx.x, b = blockIdx.y, d = threadIdx.x;
    float m1[15], mb1[3], m2[3];
    #pragma unroll
    for (int k = 0; k < 15; k++) m1[k] = __ldg(&mr1W[k]);
    #pragma unroll
    for (int k = 0; k < 3; k++) { mb1[k] = __ldg(&mr1b[k]); m2[k] = __ldg(&mr2W[k]); }
    float mb2 = __ldg(mr2b);
    int t0 = ch * 50;
    float a = 1.f, bb = 0.f;
    for (int j = 0; j < 50; j++) {
        float g = gate_val(b, t0 + j, d, m1, mb1, m2, mb2);
        float z = g_z[(b * 2000 + t0 + j) * 300 + d];
        a *= g;
        bb = g * (bb - z) + z;
    }
    int o = (b * 40 + ch) * 300 + d;
    g_scA[o] = a;
    g_scB[o] = bb;
}
__global__ void scanB_kernel() {
    int b = blockIdx.x, d = threadIdx.x;
    float c = 0.f;
    for (int ch = 0; ch < 40; ch++) {
        int o = (b * 40 + ch) * 300 + d;
        g_scC[o] = c;
        c = g_scA[o] * c + g_scB[o];
    }
}
__global__ void scanC_kernel(const float* __restrict__ mr1W, const float* __restrict__ mr1b,
                             const float* __restrict__ mr2W, const float* __restrict__ mr2b) {
    int ch = blockIdx.x, b = blockIdx.y, d = threadIdx.x;
    float m1[15], mb1[3], m2[3];
    #pragma unroll
    for (int k = 0; k < 15; k++) m1[k] = __ldg(&mr1W[k]);
    #pragma unroll
    for (int k = 0; k < 3; k++) { mb1[k] = __ldg(&mr1b[k]); m2[k] = __ldg(&mr2W[k]); }
    float mb2 = __ldg(mr2b);
    float c = g_scC[(b * 40 + ch) * 300 + d];
    int t0 = ch * 50;
    for (int j = 0; j < 50; j++) {
        int t = t0 + j;
        float g = gate_val(b, t, d, m1, mb1, m2, mb2);
        float z = g_z[(b * 2000 + t) * 300 + d];
        c = g * (c - z) + z;
        float enc = g_o[(b * 2000 + t) * 300 + d] * c;
        bf16 hb, lb; split2(enc, hb, lb);
        int o = (b * 2048 + t) * KP + d;
        g_ench[o] = hb; g_encl[o] = lb;
    }
}

// ---------------- fused: softmax30 -> P.QK -> group softmax16 -> column sums ----------------
__global__ void attn_fused() {
    __shared__ float sQK[30 * 128];
    __shared__ float sacc[128];
    int ch = blockIdx.x, b = blockIdx.y;
    int tid = threadIdx.x, warp = tid >> 5, lane = tid & 31;
    for (int i = tid; i < 30 * 128; i += 256) sQK[i] = g_QK[b * 3840 + i];
    if (tid < 128) sacc[tid] = 0.f;
    __syncthreads();
    float lacc[4] = {0.f, 0.f, 0.f, 0.f};
    for (int t = ch * 250 + warp; t < ch * 250 + 250; t += 8) {
        const float* sr = g_s1 + (size_t)(b * 2048 + t) * 32;
        float sc = (lane < 30) ? sr[lane] : -1e30f;
        float mx = sc;
        #pragma unroll
        for (int o = 16; o; o >>= 1) mx = fmaxf(mx, __shfl_xor_sync(0xffffffffu, mx, o));
        float e = (lane < 30) ? expf(sc - mx) : 0.f;
        float sm = e;
        #pragma unroll
        for (int o = 16; o; o >>= 1) sm += __shfl_xor_sync(0xffffffffu, sm, o);
        float p = e / sm;
        float s0 = 0.f, s1v = 0.f, s2v = 0.f, s3v = 0.f;
        #pragma unroll 6
        for (int w = 0; w < 30; w++) {
            float pw = __shfl_sync(0xffffffffu, p, w);
            const float* qk = sQK + w * 128 + lane * 4;
            s0 += pw * qk[0]; s1v += pw * qk[1]; s2v += pw * qk[2]; s3v += pw * qk[3];
        }
        float gm = fmaxf(fmaxf(s0, s1v), fmaxf(s2v, s3v));
        gm = fmaxf(gm, __shfl_xor_sync(0xffffffffu, gm, 1));
        gm = fmaxf(gm, __shfl_xor_sync(0xffffffffu, gm, 2));
        float e0 = expf(s0 - gm), e1 = expf(s1v - gm), e2 = expf(s2v - gm), e3 = expf(s3v - gm);
        float gs = e0 + e1 + e2 + e3;
        gs += __shfl_xor_sync(0xffffffffu, gs, 1);
        gs += __shfl_xor_sync(0xffffffffu, gs, 2);
        float inv = 1.f / gs;
        lacc[0] += e0 * inv; lacc[1] += e1 * inv; lacc[2] += e2 * inv; lacc[3] += e3 * inv;
    }
    #pragma unroll
    for (int j = 0; j < 4; j++) atomicAdd(&sacc[lane * 4 + j], lacc[j]);
    __syncthreads();
    if (tid < 128) {
        int kk = tid;
        int proj = kk >> 6, r = kk & 63;
        int opt = r >> 4, w = r & 15;
        atomicAdd(&g_cm[((opt * 16 + b) * 2 + proj) * 16 + w], sacc[kk]);
    }
}

__global__ void zero_cm_kernel() {
    int i = blockIdx.x * blockDim.x + threadIdx.x;
    if (i < 4 * 16 * 2 * 16) g_cm[i] = 0.f;
}

// ---------------- final MLP ----------------
__global__ void final_kernel(const float* __restrict__ as1W, const float* __restrict__ as1b,
                             const float* __restrict__ as2W, const float* __restrict__ as2b,
                             float* __restrict__ out) {
    __shared__ float sav[600];
    __shared__ float sh[75];
    __shared__ float scm[32];
    int bid = blockIdx.x;
    int opt = bid >> 4, b = bid & 15;
    int ob = opt * 16 + b;
    int tid = threadIdx.x;
    if (tid < 32) scm[tid] = g_cm[ob * 32 + tid] * (1.0f / 2000.0f);
    __syncthreads();
    for (int d = tid; d < 300; d += 128) {
        float a2 = 0.f, a3 = 0.f;
        #pragma unroll
        for (int w = 0; w < 16; w++) {
            float ov = g_optf[(ob * 16 + w) * 300 + d];
            a2 += scm[w] * ov;
            a3 += scm[16 + w] * ov;
        }
        sav[d] = a2;
        sav[300 + d] = a3;
    }
    __syncthreads();
    for (int j = tid; j < 75; j += 128) {
        float a = __ldg(&as1b[j]);
        for (int i2 = 0; i2 < 600; i2++) a += __ldg(&as1W[j * 600 + i2]) * sav[i2];
        sh[j] = fmaxf(a, 0.f);
    }
    __syncthreads();
    if (tid == 0) {
        float s = __ldg(as2b);
        for (int j = 0; j < 75; j++) s += __ldg(&as2W[j]) * sh[j];
        out[b * 4 + opt] = s;
    }
}

// ---------------- launch ----------------
extern "C" void kernel_launch(void* const* d_in, const int* in_sizes, int n_in,
                              void* d_out, int out_size) {
    const int* opt_idx[4] = {(const int*)d_in[0], (const int*)d_in[1],
                             (const int*)d_in[2], (const int*)d_in[3]};
    const int* q_idx = (const int*)d_in[4];
    const int* a_idx = (const int*)d_in[5];
    const float* emb = (const float*)d_in[6];
    const float* ceW = (const float*)d_in[7];
    const float* ceb = (const float*)d_in[8];
    const float* mr1W = (const float*)d_in[9];
    const float* mr1b = (const float*)d_in[10];
    const float* mr2W = (const float*)d_in[11];
    const float* mr2b = (const float*)d_in[12];
    const float* Wz = (const float*)d_in[13];
    const float* bz = (const float*)d_in[14];
    const float* Wo = (const float*)d_in[15];
    const float* bo = (const float*)d_in[16];
    const float* f1W = (const float*)d_in[17];
    const float* f1b = (const float*)d_in[18];
    const float* f2W = (const float*)d_in[19];
    const float* f2b = (const float*)d_in[20];
    const float* f3W = (const float*)d_in[21];
    const float* f3b = (const float*)d_in[22];
    const float* as1W = (const float*)d_in[23];
    const float* as1b = (const float*)d_in[24];
    const float* as2W = (const float*)d_in[25];
    const float* as2b = (const float*)d_in[26];

    static bool attrSet = false;
    if (!attrSet) {
        cudaFuncSetAttribute(gemm_mma, cudaFuncAttributeMaxDynamicSharedMemorySize, GEMM_SMEM);
        attrSet = true;
    }

    split_w<<<(450000 + 255) / 256, 256>>>(ceW, 0, 450000);
    gather_split<<<(32000 * 300 + 255) / 256, 256>>>(a_idx, emb, 0, 0, 32000);
    xs_kernel<<<(28672 * 300 + 255) / 256, 256>>>();
    split_w<<<(90000 + 255) / 256, 256>>>(Wz, 5, 90000);
    split_w<<<(90000 + 255) / 256, 256>>>(Wo, 6, 90000);
    gemm_mma<<<dim3(5, 474), 256, GEMM_SMEM>>>(0, 0, ceb, 0, 60672, 1, 1);

    split_w<<<(90000 + 255) / 256, 256>>>(f1W, 7, 90000);
    split_w<<<(90000 + 255) / 256, 256>>>(f2W, 8, 90000);
    split_w<<<(90000 + 255) / 256, 256>>>(f3W, 9, 90000);
    gather_split<<<(480 * 300 + 255) / 256, 256>>>(q_idx, emb, 1, 0, 480);
    for (int o = 0; o < 4; o++)
        gather_split<<<(256 * 300 + 255) / 256, 256>>>(opt_idx[o], emb, 2, o * 256, 256);

    // z, o projections (tanh)
    gemm_mma<<<dim3(5, 250), 256, GEMM_SMEM>>>(0, 5, bz, 1, 32000, 2, 0);
    gemm_mma<<<dim3(5, 250), 256, GEMM_SMEM>>>(0, 6, bo, 2, 32000, 2, 0);

    // chunked scan (gate fused) -> enc split
    scanA_kernel<<<dim3(40, 16), 300>>>(mr1W, mr1b, mr2W, mr2b);
    scanB_kernel<<<16, 300>>>();
    scanC_kernel<<<dim3(40, 16), 300>>>(mr1W, mr1b, mr2W, mr2b);

    // f1 keys (split, per-batch) then attn1 scores GEMM
    gemm_mma<<<dim3(5, 4), 256, GEMM_SMEM>>>(1, 7, f1b, 0, 480, 4, 0);
    gemm_mma<<<dim3(1, 256), 256, GEMM_SMEM>>>(3, 0, nullptr, 5, 32768, 3, 2);

    // option keys (split, per-batch) + QK GEMM + fused attention-2
    gemm_mma<<<dim3(5, 8), 256, GEMM_SMEM>>>(2, 8, f2b, 0, 1024, 5, 0);
    gemm_mma<<<dim3(5, 8), 256, GEMM_SMEM>>>(2, 9, f3b, 1, 1024, 5, 0);
    gemm_mma<<<dim3(2, 16), 256, GEMM_SMEM>>>(4, 0, nullptr, 5, 2048, 6, 3);
    zero_cm_kernel<<<8, 256>>>();
    attn_fused<<<dim3(8, 16), 256>>>();

    // final MLP
    final_kernel<<<64, 128>>>(as1W, as1b, as2W, as2b, (float*)d_out);
}

// round 12
// speedup vs baseline: 1.5429x; 1.0557x over previous
#include <cuda_runtime.h>
#include <cuda_bf16.h>
#include <math.h>

// DIM=300 (K padded to 304 = 19 k16 stages), B=16, T=2000, Tq=30, Topt=16
#define KP 304
#define NSTAGE 19
// CE padded row layout (128-aligned range starts): 0,32000,48000,56064,59392; M=60672

typedef __nv_bfloat16 bf16;

// ---------------- scratch ----------------
__device__ bf16  g_xsh[60672 * KP], g_xsl[60672 * KP];   // rows 0..32000 = article split
__device__ float g_h[60672 * 300];
__device__ float g_z[32000 * 300];
__device__ float g_o[32000 * 300];
__device__ bf16  g_ench[32768 * KP], g_encl[32768 * KP]; // rows b*2048+t (pad rows stay 0)
__device__ float g_s1[32768 * 32];                       // attn1 scores
__device__ bf16  g_qh[512 * KP], g_ql[512 * KP];         // rows b*30+w (f1-keys GEMM A)
__device__ bf16  g_qph[2048 * KP], g_qpl[2048 * KP];     // rows b*128+w1 (QK GEMM A, pads 0)
__device__ float g_optf[1024 * 300];
__device__ bf16  g_opth[1024 * KP], g_optl[1024 * KP];
__device__ bf16  g_kb1h[16 * 64 * KP], g_kb1l[16 * 64 * KP];   // f1 keys per batch (rows 30..63 zero)
__device__ bf16  g_kb2h[16 * 128 * KP], g_kb2l[16 * 128 * KP]; // f2/f3 keys per batch
__device__ float g_QK[16 * 30 * 128];
__device__ float g_scA[16 * 40 * 300], g_scB[16 * 40 * 300], g_scC[16 * 40 * 300];
__device__ float g_cm[4 * 16 * 2 * 16];
// weight slots [320][KP]: 0-4 ce, 5 Wz, 6 Wo, 7 f1, 8 f2, 9 f3
#define WSLOT (320 * KP)
__device__ bf16 g_wh[10 * WSLOT], g_wl[10 * WSLOT];

// ---------------- helpers ----------------
__device__ __forceinline__ void split2(float x, bf16& h, bf16& l) {
    h = __float2bfloat16(x);
    l = __float2bfloat16(x - __bfloat162float(h));
}
__device__ __forceinline__ void cp16(void* s, const void* g) {
    unsigned sa = (unsigned)__cvta_generic_to_shared(s);
    asm volatile("cp.async.cg.shared.global [%0], [%1], 16;" :: "r"(sa), "l"(g));
}
__device__ __forceinline__ void mma16816(float* c, const unsigned* a, const unsigned* b) {
    asm volatile(
        "mma.sync.aligned.m16n8k16.row.col.f32.bf16.bf16.f32 "
        "{%0,%1,%2,%3}, {%4,%5,%6,%7}, {%8,%9}, {%0,%1,%2,%3};\n"
        : "+f"(c[0]), "+f"(c[1]), "+f"(c[2]), "+f"(c[3])
        : "r"(a[0]), "r"(a[1]), "r"(a[2]), "r"(a[3]), "r"(b[0]), "r"(b[1]));
}
__device__ __forceinline__ void ldsm4(unsigned& r0, unsigned& r1, unsigned& r2, unsigned& r3,
                                      unsigned addr) {
    asm volatile("ldmatrix.sync.aligned.m8n8.x4.shared.b16 {%0,%1,%2,%3}, [%4];"
                 : "=r"(r0), "=r"(r1), "=r"(r2), "=r"(r3) : "r"(addr));
}

// ---------------- weight prep ----------------
__global__ void split_w(const float* __restrict__ src, int slotBase, int count) {
    int i = blockIdx.x * blockDim.x + threadIdx.x;
    if (i >= count) return;
    int slot = slotBase + i / 90000;
    int rem = i % 90000;
    int n = rem / 300, k = rem - n * 300;
    bf16 h, l; split2(src[i], h, l);
    int o = slot * WSLOT + n * KP + k;
    g_wh[o] = h; g_wl[o] = l;
}
__global__ void split_w2(const float* __restrict__ a, const float* __restrict__ b, int slotA) {
    int i = blockIdx.x * blockDim.x + threadIdx.x;
    if (i >= 180000) return;
    float x = (i < 90000) ? a[i] : b[i - 90000];
    int slot = slotA + i / 90000;
    int rem = i % 90000;
    int n = rem / 300, k = rem - n * 300;
    bf16 h, l; split2(x, h, l);
    int o = slot * WSLOT + n * KP + k;
    g_wh[o] = h; g_wl[o] = l;
}
__global__ void split_w3(const float* __restrict__ a, const float* __restrict__ b,
                         const float* __restrict__ c, int slotA) {
    int i = blockIdx.x * blockDim.x + threadIdx.x;
    if (i >= 270000) return;
    int which = i / 90000;
    int rem = i % 90000;
    float x = (which == 0) ? a[rem] : (which == 1) ? b[rem] : c[rem];
    int n = rem / 300, k = rem - n * 300;
    int o = (slotA + which) * WSLOT + n * KP + k;
    bf16 h, l; split2(x, h, l);
    g_wh[o] = h; g_wl[o] = l;
}

// ---------------- embedding gather + split ----------------
__global__ void gather_split(const int* __restrict__ idx, const float* __restrict__ emb,
                             int sel, int rowOff, int nrows) {
    int i = blockIdx.x * blockDim.x + threadIdx.x;
    if (i >= nrows * 300) return;
    int r = i / 300, d = i - r * 300;
    float x = emb[idx[r] * 300 + d];
    int R = rowOff + r;
    bf16 hb, lb; split2(x, hb, lb);
    if (sel == 0) {          // article: split straight into xs rows (r=1 block)
        g_xsh[R * KP + d] = hb; g_xsl[R * KP + d] = lb;
    } else if (sel == 1) {   // question: compact rows + per-batch padded rows
        g_qh[R * KP + d] = hb; g_ql[R * KP + d] = lb;
        int b = R / 30, w1 = R - b * 30;
        int o = (b * 128 + w1) * KP + d;
        g_qph[o] = hb; g_qpl[o] = lb;
    } else {                 // options
        g_optf[R * 300 + d] = x;
        g_opth[R * KP + d] = hb; g_optl[R * KP + d] = lb;
    }
}

// ---------------- group sums for r>=2 ranges (reads article from split rows) ----------------
__device__ __forceinline__ float artval(int row, int d) {
    int o = row * KP + d;
    return __bfloat162float(g_xsh[o]) + __bfloat162float(g_xsl[o]);
}
__global__ void xs_kernel() {
    int i = blockIdx.x * blockDim.x + threadIdx.x;
    if (i >= 28672 * 300) return;
    int R = 32000 + i / 300, d = i % 300;
    float s;
    if (R < 48000) {
        int L = R - 32000, b = L / 1000, g = L - b * 1000;
        int base = b * 2000 + g * 2;
        s = artval(base, d) + artval(base + 1, d);
    } else if (R < 56000) {
        int L = R - 48000, b = L / 500, g = L - b * 500;
        int base = b * 2000 + g * 4;
        s = 0.f;
        #pragma unroll
        for (int j = 0; j < 4; j++) s += artval(base + j, d);
    } else if (R < 56064) return;
    else if (R < 59264) {
        int L = R - 56064, b = L / 200, g = L - b * 200;
        int base = b * 2000 + g * 10;
        s = 0.f;
        #pragma unroll
        for (int j = 0; j < 10; j++) s += artval(base + j, d);
    } else if (R < 59392) return;
    else {
        int L = R - 59392, b = L / 80, g = L - b * 80;
        int base = b * 2000 + g * 25;
        s = 0.f;
        #pragma unroll
        for (int j = 0; j < 25; j++) s += artval(base + j, d);
    }
    bf16 h, l; split2(s, h, l);
    g_xsh[R * KP + d] = h;
    g_xsl[R * KP + d] = l;
}

// ---------------- tensor-core GEMM ----------------
// C = act(A(M,300) @ W(300,300)^T + bias); bf16 2-split (hh+hl+lh).
// 3-stage cp.async pipeline, ldmatrix fragment loads, one __syncthreads per stage.
// wmode: 0 slot, 1 CE per-range, 2 f1 keys per batch (bm>>11), 3 f2/f3 keys per batch (bm>>7)
// act: 0 none /1 relu /2 tanh (fp32 C stride 300); 3 scores (fp32 stride 32, n<32, no bias);
//      4 f1-key split -> g_kb1; 5 f2/f3-key split -> g_kb2 (proj = wslot-8);
//      6 QK epilogue -> g_QK (also zeroes g_cm from block y==0);
//      7 merged z/o: cols 0-299 -> z (bias), 320-619 -> o (bias2)
#define SAST 24
#define APL (128 * SAST)
#define BPL (64 * SAST)
#define STG (2 * APL + 2 * BPL)
#define GEMM_SMEM (3 * STG * 2)

__global__ void __launch_bounds__(256) gemm_mma(int Asel, int wslot, const float* __restrict__ bias,
                                                const float* __restrict__ bias2,
                                                int Csel, int M, int act, int wmode) {
    extern __shared__ __align__(16) bf16 sdy[];

    if (act == 6 && blockIdx.y == 0) {  // fold g_cm zeroing into the QK GEMM
        for (int i = threadIdx.x; i < 2048; i += 256) g_cm[i] = 0.f;
    }

    const bf16 *Ah, *Al;
    switch (Asel) {
        case 0: Ah = g_xsh;  Al = g_xsl;  break;
        case 1: Ah = g_qh;   Al = g_ql;   break;
        case 2: Ah = g_opth; Al = g_optl; break;
        case 4: Ah = g_qph;  Al = g_qpl;  break;
        default: Ah = g_ench; Al = g_encl; break;
    }
    float* C;
    switch (Csel) {
        case 0: C = g_h;  break;
        default: C = g_s1; break;
    }
    int bm = blockIdx.y * 128, bn = blockIdx.x * 64;
    const bf16 *Wh, *Wl;
    if (wmode == 1) {
        int slot = (bm < 32000) ? 0 : (bm < 48000) ? 1 : (bm < 56064) ? 2 : (bm < 59392) ? 3 : 4;
        bias += slot * 300;
        Wh = g_wh + slot * WSLOT; Wl = g_wl + slot * WSLOT;
    } else if (wmode == 2) {
        int b = bm >> 11;
        Wh = g_kb1h + b * 64 * KP; Wl = g_kb1l + b * 64 * KP;
    } else if (wmode == 3) {
        int b = bm >> 7;
        Wh = g_kb2h + b * 128 * KP; Wl = g_kb2l + b * 128 * KP;
    } else {
        Wh = g_wh + wslot * WSLOT; Wl = g_wl + wslot * WSLOT;
    }

    int tid = threadIdx.x;
    int lane = tid & 31, warp = tid >> 5;
    int wm = warp & 3, wn = warp >> 2;

    auto issue = [&](int s, int buf) {
        int kt = s * 16;
        bf16* base = sdy + buf * STG;
        int row = tid >> 1, kh = (tid & 1) * 8;
        cp16(base + row * SAST + kh, Ah + (size_t)(bm + row) * KP + kt + kh);
        cp16(base + APL + row * SAST + kh, Al + (size_t)(bm + row) * KP + kt + kh);
        if (tid < 128) {
            int br = tid >> 1, bkh = (tid & 1) * 8;
            cp16(base + 2 * APL + br * SAST + bkh, Wh + (size_t)(bn + br) * KP + kt + bkh);
        } else {
            int t = tid - 128;
            int br = t >> 1, bkh = (t & 1) * 8;
            cp16(base + 2 * APL + BPL + br * SAST + bkh, Wl + (size_t)(bn + br) * KP + kt + bkh);
        }
        asm volatile("cp.async.commit_group;");
    };

    float acc[2][4][4];
    #pragma unroll
    for (int mi = 0; mi < 2; mi++)
        #pragma unroll
        for (int ni = 0; ni < 4; ni++)
            #pragma unroll
            for (int j = 0; j < 4; j++) acc[mi][ni][j] = 0.f;

    unsigned sbase = (unsigned)__cvta_generic_to_shared(sdy);
    unsigned aInv0 = (unsigned)((wm * 32 + (lane & 15)) * SAST + (lane >> 4) * 8);
    unsigned aInv1 = aInv0 + 16 * SAST;
    unsigned bInv0 = (unsigned)(2 * APL +
                     (wn * 32 + ((lane >> 4) & 1) * 8 + (lane & 7)) * SAST + ((lane >> 3) & 1) * 8);
    unsigned bInv1 = bInv0 + 16 * SAST;

    issue(0, 0);
    issue(1, 1);

    for (int s = 0; s < NSTAGE; s++) {
        if (s < NSTAGE - 1) asm volatile("cp.async.wait_group 1;");
        else                asm volatile("cp.async.wait_group 0;");
        __syncthreads();
        int buf = s % 3;
        unsigned bb = (unsigned)(buf * STG);
        unsigned ah[2][4], al[2][4], bh[4][2], bl[4][2];
        ldsm4(ah[0][0], ah[0][1], ah[0][2], ah[0][3], sbase + (bb + aInv0) * 2);
        ldsm4(ah[1][0], ah[1][1], ah[1][2], ah[1][3], sbase + (bb + aInv1) * 2);
        ldsm4(al[0][0], al[0][1], al[0][2], al[0][3], sbase + (bb + APL + aInv0) * 2);
        ldsm4(al[1][0], al[1][1], al[1][2], al[1][3], sbase + (bb + APL + aInv1) * 2);
        ldsm4(bh[0][0], bh[0][1], bh[1][0], bh[1][1], sbase + (bb + bInv0) * 2);
        ldsm4(bh[2][0], bh[2][1], bh[3][0], bh[3][1], sbase + (bb + bInv1) * 2);
        ldsm4(bl[0][0], bl[0][1], bl[1][0], bl[1][1], sbase + (bb + BPL + bInv0) * 2);
        ldsm4(bl[2][0], bl[2][1], bl[3][0], bl[3][1], sbase + (bb + BPL + bInv1) * 2);
        #pragma unroll
        for (int mi = 0; mi < 2; mi++)
            #pragma unroll
            for (int ni = 0; ni < 4; ni++) {
                mma16816(acc[mi][ni], ah[mi], bh[ni]);
                mma16816(acc[mi][ni], ah[mi], bl[ni]);
                mma16816(acc[mi][ni], al[mi], bh[ni]);
            }
        if (s + 2 < NSTAGE) issue(s + 2, (s + 2) % 3);
    }

    // epilogue
    #pragma unroll
    for (int mi = 0; mi < 2; mi++) {
        int mrow = bm + wm * 32 + mi * 16 + (lane >> 2);
        #pragma unroll
        for (int ni = 0; ni < 4; ni++) {
            int ncol = bn + wn * 32 + ni * 8 + 2 * (lane & 3);
            #pragma unroll
            for (int rr = 0; rr < 2; rr++) {
                int m = mrow + rr * 8;
                #pragma unroll
                for (int cc = 0; cc < 2; cc++) {
                    int n = ncol + cc;
                    float v = acc[mi][ni][rr * 2 + cc];
                    if (act == 3) {
                        if (m < M && n < 32) C[(size_t)m * 32 + n] = v;
                    } else if (act == 4) {
                        if (m < 480 && n < 300) {
                            v += __ldg(&bias[n]);
                            int b = m / 30, w = m - b * 30;
                            bf16 hb, lb; split2(v, hb, lb);
                            int o = (b * 64 + w) * KP + n;
                            g_kb1h[o] = hb; g_kb1l[o] = lb;
                        }
                    } else if (act == 5) {
                        if (m < 1024 && n < 300) {
                            v += __ldg(&bias[n]);
                            int b = (m >> 4) & 15, opt = m >> 8, w = m & 15;
                            int kk = (wslot - 8) * 64 + opt * 16 + w;
                            bf16 hb, lb; split2(v, hb, lb);
                            int o = (b * 128 + kk) * KP + n;
                            g_kb2h[o] = hb; g_kb2l[o] = lb;
                        }
                    } else if (act == 6) {
                        int w1 = m & 127;
                        if (m < 2048 && w1 < 30 && n < 128)
                            g_QK[(m >> 7) * 3840 + w1 * 128 + n] = v;
                    } else if (act == 7) {
                        if (m < M) {
                            if (n < 300) {
                                g_z[(size_t)m * 300 + n] = tanhf(v + __ldg(&bias[n]));
                            } else if (n >= 320 && n < 620) {
                                int n2 = n - 320;
                                g_o[(size_t)m * 300 + n2] = tanhf(v + __ldg(&bias2[n2]));
                            }
                        }
                    } else {
                        if (m < M && n < 300) {
                            v += __ldg(&bias[n]);
                            if (act == 1) v = fmaxf(v, 0.f);
                            else if (act == 2) v = tanhf(v);
                            C[(size_t)m * 300 + n] = v;
                        }
                    }
                }
            }
        }
    }
}

// ---------------- fused gate evaluation ----------------
__device__ __forceinline__ float gate_val(int b, int t, int d, const float* m1,
                                          const float* mb1, const float* m2, float mb2) {
    float y0 = g_h[(b * 2000 + t) * 300 + d];
    float y1 = g_h[(32000 + b * 1000 + (t >> 1)) * 300 + d] * 0.5f;
    float y2 = g_h[(48000 + b * 500 + (t >> 2)) * 300 + d] * 0.25f;
    float y3 = g_h[(56064 + b * 200 + t / 10) * 300 + d] * (1.0f / 10.0f);
    float y4 = g_h[(59392 + b * 80 + t / 25) * 300 + d] * (1.0f / 25.0f);
    float acc = mb2;
    #pragma unroll
    for (int k = 0; k < 3; k++) {
        float hk = mb1[k] + m1[k * 5] * y0 + m1[k * 5 + 1] * y1 + m1[k * 5 + 2] * y2
                 + m1[k * 5 + 3] * y3 + m1[k * 5 + 4] * y4;
        acc += m2[k] * fmaxf(hk, 0.f);
    }
    return fmaxf(acc, 0.f);
}

// ---------------- chunked linear scan (gate fused) ----------------
__global__ void scanA_kernel(const float* __restrict__ mr1W, const float* __restrict__ mr1b,
                             const float* __restrict__ mr2W, const float* __restrict__ mr2b) {
    int ch = blockIdx.x, b = blockIdx.y, d = threadIdx.x;
    float m1[15], mb1[3], m2[3];
    #pragma unroll
    for (int k = 0; k < 15; k++) m1[k] = __ldg(&mr1W[k]);
    #pragma unroll
    for (int k = 0; k < 3; k++) { mb1[k] = __ldg(&mr1b[k]); m2[k] = __ldg(&mr2W[k]); }
    float mb2 = __ldg(mr2b);
    int t0 = ch * 50;
    float a = 1.f, bb = 0.f;
    for (int j = 0; j < 50; j++) {
        float g = gate_val(b, t0 + j, d, m1, mb1, m2, mb2);
        float z = g_z[(b * 2000 + t0 + j) * 300 + d];
        a *= g;
        bb = g * (bb - z) + z;
    }
    int o = (b * 40 + ch) * 300 + d;
    g_scA[o] = a;
    g_scB[o] = bb;
}
__global__ void scanB_kernel() {
    int b = blockIdx.x, d = threadIdx.x;
    float c = 0.f;
    for (int ch = 0; ch < 40; ch++) {
        int o = (b * 40 + ch) * 300 + d;
        g_scC[o] = c;
        c = g_scA[o] * c + g_scB[o];
    }
}
__global__ void scanC_kernel(const float* __restrict__ mr1W, const float* __restrict__ mr1b,
                             const float* __restrict__ mr2W, const float* __restrict__ mr2b) {
    int ch = blockIdx.x, b = blockIdx.y, d = threadIdx.x;
    float m1[15], mb1[3], m2[3];
    #pragma unroll
    for (int k = 0; k < 15; k++) m1[k] = __ldg(&mr1W[k]);
    #pragma unroll
    for (int k = 0; k < 3; k++) { mb1[k] = __ldg(&mr1b[k]); m2[k] = __ldg(&mr2W[k]); }
    float mb2 = __ldg(mr2b);
    float c = g_scC[(b * 40 + ch) * 300 + d];
    int t0 = ch * 50;
    for (int j = 0; j < 50; j++) {
        int t = t0 + j;
        float g = gate_val(b, t, d, m1, mb1, m2, mb2);
        float z = g_z[(b * 2000 + t) * 300 + d];
        c = g * (c - z) + z;
        float enc = g_o[(b * 2000 + t) * 300 + d] * c;
        bf16 hb, lb; split2(enc, hb, lb);
        int o = (b * 2048 + t) * KP + d;
        g_ench[o] = hb; g_encl[o] = lb;
    }
}

// ---------------- fused: softmax30 -> P.QK -> group softmax16 -> column sums ----------------
__global__ void attn_fused() {
    __shared__ float sQK[30 * 128];
    __shared__ float sacc[128];
    int ch = blockIdx.x, b = blockIdx.y;
    int tid = threadIdx.x, warp = tid >> 5, lane = tid & 31;
    for (int i = tid; i < 30 * 128; i += 256) sQK[i] = g_QK[b * 3840 + i];
    if (tid < 128) sacc[tid] = 0.f;
    __syncthreads();
    float lacc[4] = {0.f, 0.f, 0.f, 0.f};
    for (int t = ch * 250 + warp; t < ch * 250 + 250; t += 8) {
        const float* sr = g_s1 + (size_t)(b * 2048 + t) * 32;
        float sc = (lane < 30) ? sr[lane] : -1e30f;
        float mx = sc;
        #pragma unroll
        for (int o = 16; o; o >>= 1) mx = fmaxf(mx, __shfl_xor_sync(0xffffffffu, mx, o));
        float e = (lane < 30) ? expf(sc - mx) : 0.f;
        float sm = e;
        #pragma unroll
        for (int o = 16; o; o >>= 1) sm += __shfl_xor_sync(0xffffffffu, sm, o);
        float p = e / sm;
        float s0 = 0.f, s1v = 0.f, s2v = 0.f, s3v = 0.f;
        #pragma unroll 6
        for (int w = 0; w < 30; w++) {
            float pw = __shfl_sync(0xffffffffu, p, w);
            const float* qk = sQK + w * 128 + lane * 4;
            s0 += pw * qk[0]; s1v += pw * qk[1]; s2v += pw * qk[2]; s3v += pw * qk[3];
        }
        float gm = fmaxf(fmaxf(s0, s1v), fmaxf(s2v, s3v));
        gm = fmaxf(gm, __shfl_xor_sync(0xffffffffu, gm, 1));
        gm = fmaxf(gm, __shfl_xor_sync(0xffffffffu, gm, 2));
        float e0 = expf(s0 - gm), e1 = expf(s1v - gm), e2 = expf(s2v - gm), e3 = expf(s3v - gm);
        float gs = e0 + e1 + e2 + e3;
        gs += __shfl_xor_sync(0xffffffffu, gs, 1);
        gs += __shfl_xor_sync(0xffffffffu, gs, 2);
        float inv = 1.f / gs;
        lacc[0] += e0 * inv; lacc[1] += e1 * inv; lacc[2] += e2 * inv; lacc[3] += e3 * inv;
    }
    #pragma unroll
    for (int j = 0; j < 4; j++) atomicAdd(&sacc[lane * 4 + j], lacc[j]);
    __syncthreads();
    if (tid < 128) {
        int kk = tid;
        int proj = kk >> 6, r = kk & 63;
        int opt = r >> 4, w = r & 15;
        atomicAdd(&g_cm[((opt * 16 + b) * 2 + proj) * 16 + w], sacc[kk]);
    }
}

// ---------------- final MLP ----------------
__global__ void final_kernel(const float* __restrict__ as1W, const float* __restrict__ as1b,
                             const float* __restrict__ as2W, const float* __restrict__ as2b,
                             float* __restrict__ out) {
    __shared__ float sav[600];
    __shared__ float sh[75];
    __shared__ float scm[32];
    int bid = blockIdx.x;
    int opt = bid >> 4, b = bid & 15;
    int ob = opt * 16 + b;
    int tid = threadIdx.x;
    if (tid < 32) scm[tid] = g_cm[ob * 32 + tid] * (1.0f / 2000.0f);
    __syncthreads();
    for (int d = tid; d < 300; d += 128) {
        float a2 = 0.f, a3 = 0.f;
        #pragma unroll
        for (int w = 0; w < 16; w++) {
            float ov = g_optf[(ob * 16 + w) * 300 + d];
            a2 += scm[w] * ov;
            a3 += scm[16 + w] * ov;
        }
        sav[d] = a2;
        sav[300 + d] = a3;
    }
    __syncthreads();
    for (int j = tid; j < 75; j += 128) {
        float a = __ldg(&as1b[j]);
        for (int i2 = 0; i2 < 600; i2++) a += __ldg(&as1W[j * 600 + i2]) * sav[i2];
        sh[j] = fmaxf(a, 0.f);
    }
    __syncthreads();
    if (tid == 0) {
        float s = __ldg(as2b);
        for (int j = 0; j < 75; j++) s += __ldg(&as2W[j]) * sh[j];
        out[b * 4 + opt] = s;
    }
}

// ---------------- launch ----------------
extern "C" void kernel_launch(void* const* d_in, const int* in_sizes, int n_in,
                              void* d_out, int out_size) {
    const int* opt_idx[4] = {(const int*)d_in[0], (const int*)d_in[1],
                             (const int*)d_in[2], (const int*)d_in[3]};
    const int* q_idx = (const int*)d_in[4];
    const int* a_idx = (const int*)d_in[5];
    const float* emb = (const float*)d_in[6];
    const float* ceW = (const float*)d_in[7];
    const float* ceb = (const float*)d_in[8];
    const float* mr1W = (const float*)d_in[9];
    const float* mr1b = (const float*)d_in[10];
    const float* mr2W = (const float*)d_in[11];
    const float* mr2b = (const float*)d_in[12];
    const float* Wz = (const float*)d_in[13];
    const float* bz = (const float*)d_in[14];
    const float* Wo = (const float*)d_in[15];
    const float* bo = (const float*)d_in[16];
    const float* f1W = (const float*)d_in[17];
    const float* f1b = (const float*)d_in[18];
    const float* f2W = (const float*)d_in[19];
    const float* f2b = (const float*)d_in[20];
    const float* f3W = (const float*)d_in[21];
    const float* f3b = (const float*)d_in[22];
    const float* as1W = (const float*)d_in[23];
    const float* as1b = (const float*)d_in[24];
    const float* as2W = (const float*)d_in[25];
    const float* as2b = (const float*)d_in[26];

    static bool attrSet = false;
    if (!attrSet) {
        cudaFuncSetAttribute(gemm_mma, cudaFuncAttributeMaxDynamicSharedMemorySize, GEMM_SMEM);
        attrSet = true;
    }

    // #1-#4, then big GEMMs at #5 and #6 (ncu -s 5 -c 1 lands on one of them)
    split_w<<<(450000 + 255) / 256, 256>>>(ceW, 0, 450000);                    // 1
    gather_split<<<(32000 * 300 + 255) / 256, 256>>>(a_idx, emb, 0, 0, 32000); // 2
    xs_kernel<<<(28672 * 300 + 255) / 256, 256>>>();                           // 3
    split_w2<<<(180000 + 255) / 256, 256>>>(Wz, Wo, 5);                        // 4
    gemm_mma<<<dim3(5, 474), 256, GEMM_SMEM>>>(0, 0, ceb, nullptr, 0, 60672, 1, 1);   // 5 CE
    gemm_mma<<<dim3(10, 250), 256, GEMM_SMEM>>>(0, 5, bz, bo, 0, 32000, 7, 0);        // 6 z+o

    split_w3<<<(270000 + 255) / 256, 256>>>(f1W, f2W, f3W, 7);
    gather_split<<<(480 * 300 + 255) / 256, 256>>>(q_idx, emb, 1, 0, 480);
    for (int o = 0; o < 4; o++)
        gather_split<<<(256 * 300 + 255) / 256, 256>>>(opt_idx[o], emb, 2, o * 256, 256);

    // chunked scan (gate fused) -> enc split
    scanA_kernel<<<dim3(40, 16), 300>>>(mr1W, mr1b, mr2W, mr2b);
    scanB_kernel<<<16, 300>>>();
    scanC_kernel<<<dim3(40, 16), 300>>>(mr1W, mr1b, mr2W, mr2b);

    // f1 keys (split, per-batch) then attn1 scores GEMM
    gemm_mma<<<dim3(5, 4), 256, GEMM_SMEM>>>(1, 7, f1b, nullptr, 0, 480, 4, 0);
    gemm_mma<<<dim3(1, 256), 256, GEMM_SMEM>>>(3, 0, nullptr, nullptr, 5, 32768, 3, 2);

    // option keys (split, per-batch) + QK GEMM (zeroes g_cm) + fused attention-2
    gemm_mma<<<dim3(5, 8), 256, GEMM_SMEM>>>(2, 8, f2b, nullptr, 0, 1024, 5, 0);
    gemm_mma<<<dim3(5, 8), 256, GEMM_SMEM>>>(2, 9, f3b, nullptr, 1, 1024, 5, 0);
    gemm_mma<<<dim3(2, 16), 256, GEMM_SMEM>>>(4, 0, nullptr, nullptr, 5, 2048, 6, 3);
    attn_fused<<<dim3(8, 16), 256>>>();

    // final MLP
    final_kernel<<<64, 128>>>(as1W, as1b, as2W, as2b, (float*)d_out);
}

// round 16
// speedup vs baseline: 1.5933x; 1.0327x over previous
#include <cuda_runtime.h>
#include <cuda_bf16.h>
#include <math.h>

// DIM=300 (K padded to 304 = 19 k16 stages), B=16, T=2000, Tq=30, Topt=16
#define KP 304
#define NSTAGE 19
// CE padded row layout (128-aligned range starts): 0,32000,48000,56064,59392; M=60672

typedef __nv_bfloat16 bf16;

// ---------------- scratch ----------------
__device__ bf16  g_xsh[60672 * KP], g_xsl[60672 * KP];   // rows 0..32000 = article split
__device__ float g_h[60672 * 300];
__device__ float g_z[32000 * 300];
__device__ float g_o[32000 * 300];
__device__ bf16  g_ench[32768 * KP], g_encl[32768 * KP]; // rows b*2048+t (pad rows stay 0)
__device__ float g_s1[32768 * 32];                       // attn1 scores
__device__ bf16  g_qh[512 * KP], g_ql[512 * KP];         // rows b*30+w (f1-keys GEMM A)
__device__ bf16  g_qph[2048 * KP], g_qpl[2048 * KP];     // rows b*128+w1 (QK GEMM A, pads 0)
__device__ float g_optf[1024 * 300];
__device__ bf16  g_opth[1024 * KP], g_optl[1024 * KP];
__device__ bf16  g_kb1h[16 * 64 * KP], g_kb1l[16 * 64 * KP];   // f1 keys per batch (rows 30..63 zero)
__device__ bf16  g_kb2h[16 * 128 * KP], g_kb2l[16 * 128 * KP]; // f2/f3 keys per batch
__device__ float g_QK[16 * 30 * 128];
__device__ float g_scA[16 * 40 * 300], g_scB[16 * 40 * 300], g_scC[16 * 40 * 300];
__device__ float g_cm[4 * 16 * 2 * 16];
// weight slots [320][KP]: 0-4 ce, 5 Wz, 6 Wo, 7 f1, 8 f2, 9 f3
#define WSLOT (320 * KP)
__device__ bf16 g_wh[10 * WSLOT], g_wl[10 * WSLOT];

// ---------------- helpers ----------------
__device__ __forceinline__ void split2(float x, bf16& h, bf16& l) {
    h = __float2bfloat16(x);
    l = __float2bfloat16(x - __bfloat162float(h));
}
__device__ __forceinline__ void cp16(void* s, const void* g) {
    unsigned sa = (unsigned)__cvta_generic_to_shared(s);
    asm volatile("cp.async.cg.shared.global [%0], [%1], 16;" :: "r"(sa), "l"(g));
}
__device__ __forceinline__ void mma16816(float* c, const unsigned* a, const unsigned* b) {
    asm volatile(
        "mma.sync.aligned.m16n8k16.row.col.f32.bf16.bf16.f32 "
        "{%0,%1,%2,%3}, {%4,%5,%6,%7}, {%8,%9}, {%0,%1,%2,%3};\n"
        : "+f"(c[0]), "+f"(c[1]), "+f"(c[2]), "+f"(c[3])
        : "r"(a[0]), "r"(a[1]), "r"(a[2]), "r"(a[3]), "r"(b[0]), "r"(b[1]));
}
__device__ __forceinline__ void ldsm4(unsigned& r0, unsigned& r1, unsigned& r2, unsigned& r3,
                                      unsigned addr) {
    asm volatile("ldmatrix.sync.aligned.m8n8.x4.shared.b16 {%0,%1,%2,%3}, [%4];"
                 : "=r"(r0), "=r"(r1), "=r"(r2), "=r"(r3) : "r"(addr));
}

// ---------------- weight prep ----------------
__global__ void split_w(const float* __restrict__ src, int slotBase, int count) {
    int i = blockIdx.x * blockDim.x + threadIdx.x;
    if (i >= count) return;
    int slot = slotBase + i / 90000;
    int rem = i % 90000;
    int n = rem / 300, k = rem - n * 300;
    bf16 h, l; split2(src[i], h, l);
    int o = slot * WSLOT + n * KP + k;
    g_wh[o] = h; g_wl[o] = l;
}
__global__ void split_w2(const float* __restrict__ a, const float* __restrict__ b, int slotA) {
    int i = blockIdx.x * blockDim.x + threadIdx.x;
    if (i >= 180000) return;
    float x = (i < 90000) ? a[i] : b[i - 90000];
    int slot = slotA + i / 90000;
    int rem = i % 90000;
    int n = rem / 300, k = rem - n * 300;
    bf16 h, l; split2(x, h, l);
    int o = slot * WSLOT + n * KP + k;
    g_wh[o] = h; g_wl[o] = l;
}
__global__ void split_w3(const float* __restrict__ a, const float* __restrict__ b,
                         const float* __restrict__ c, int slotA) {
    int i = blockIdx.x * blockDim.x + threadIdx.x;
    if (i >= 270000) return;
    int which = i / 90000;
    int rem = i % 90000;
    float x = (which == 0) ? a[rem] : (which == 1) ? b[rem] : c[rem];
    int n = rem / 300, k = rem - n * 300;
    int o = (slotA + which) * WSLOT + n * KP + k;
    bf16 h, l; split2(x, h, l);
    g_wh[o] = h; g_wl[o] = l;
}

// ---------------- embedding gathers ----------------
__global__ void gather_split(const int* __restrict__ idx, const float* __restrict__ emb,
                             int sel, int rowOff, int nrows) {
    int i = blockIdx.x * blockDim.x + threadIdx.x;
    if (i >= nrows * 300) return;
    int r = i / 300, d = i - r * 300;
    float x = emb[idx[r] * 300 + d];
    int R = rowOff + r;
    bf16 hb, lb; split2(x, hb, lb);
    if (sel == 0) {          // article: split straight into xs rows (r=1 block)
        g_xsh[R * KP + d] = hb; g_xsl[R * KP + d] = lb;
    } else {                 // question: compact rows + per-batch padded rows
        g_qh[R * KP + d] = hb; g_ql[R * KP + d] = lb;
        int b = R / 30, w1 = R - b * 30;
        int o = (b * 128 + w1) * KP + d;
        g_qph[o] = hb; g_qpl[o] = lb;
    }
}
__global__ void gather_opt4(const int* __restrict__ i0, const int* __restrict__ i1,
                            const int* __restrict__ i2, const int* __restrict__ i3,
                            const float* __restrict__ emb) {
    int i = blockIdx.x * blockDim.x + threadIdx.x;
    if (i >= 4 * 256 * 300) return;
    int opt = i / 76800;
    int rem = i - opt * 76800;
    int r = rem / 300, d = rem - r * 300;
    const int* ip = (opt == 0) ? i0 : (opt == 1) ? i1 : (opt == 2) ? i2 : i3;
    float x = emb[ip[r] * 300 + d];
    int R = opt * 256 + r;
    bf16 hb, lb; split2(x, hb, lb);
    g_optf[R * 300 + d] = x;
    g_opth[R * KP + d] = hb; g_optl[R * KP + d] = lb;
}

// ---------------- group sums for r>=2 ranges (reads article from split rows) ----------------
__device__ __forceinline__ float artval(int row, int d) {
    int o = row * KP + d;
    return __bfloat162float(g_xsh[o]) + __bfloat162float(g_xsl[o]);
}
__global__ void xs_kernel() {
    int i = blockIdx.x * blockDim.x + threadIdx.x;
    if (i >= 28672 * 300) return;
    int R = 32000 + i / 300, d = i % 300;
    float s;
    if (R < 48000) {
        int L = R - 32000, b = L / 1000, g = L - b * 1000;
        int base = b * 2000 + g * 2;
        s = artval(base, d) + artval(base + 1, d);
    } else if (R < 56000) {
        int L = R - 48000, b = L / 500, g = L - b * 500;
        int base = b * 2000 + g * 4;
        s = 0.f;
        #pragma unroll
        for (int j = 0; j < 4; j++) s += artval(base + j, d);
    } else if (R < 56064) return;
    else if (R < 59264) {
        int L = R - 56064, b = L / 200, g = L - b * 200;
        int base = b * 2000 + g * 10;
        s = 0.f;
        #pragma unroll
        for (int j = 0; j < 10; j++) s += artval(base + j, d);
    } else if (R < 59392) return;
    else {
        int L = R - 59392, b = L / 80, g = L - b * 80;
        int base = b * 2000 + g * 25;
        s = 0.f;
        #pragma unroll
        for (int j = 0; j < 25; j++) s += artval(base + j, d);
    }
    bf16 h, l; split2(s, h, l);
    g_xsh[R * KP + d] = h;
    g_xsl[R * KP + d] = l;
}

// ---------------- tensor-core GEMM ----------------
// C = act(A(M,300) @ W(300,300)^T + bias); bf16 2-split (hh+hl+lh).
// 3-stage cp.async pipeline, ldmatrix fragment loads, one __syncthreads per stage.
// wmode: 0 slot, 1 CE per-range, 2 f1 keys per batch (bm>>11), 3 f2/f3 keys per batch (bm>>7)
// act: 0 none /1 relu /2 tanh (fp32 C stride 300); 3 scores (fp32 stride 32, n<32, no bias);
//      4 f1-key split -> g_kb1; 5 merged f2/f3-key split -> g_kb2 (proj from col, f3 bias=bias2);
//      6 QK epilogue -> g_QK (also zeroes g_cm from block y==0);
//      7 merged z/o: cols 0-299 -> z (bias), 320-619 -> o (bias2)
#define SAST 24
#define APL (128 * SAST)
#define BPL (64 * SAST)
#define STG (2 * APL + 2 * BPL)
#define GEMM_SMEM (3 * STG * 2)

__global__ void __launch_bounds__(256) gemm_mma(int Asel, int wslot, const float* __restrict__ bias,
                                                const float* __restrict__ bias2,
                                                int Csel, int M, int act, int wmode) {
    extern __shared__ __align__(16) bf16 sdy[];

    if (act == 6 && blockIdx.y == 0) {  // fold g_cm zeroing into the QK GEMM
        for (int i = threadIdx.x; i < 2048; i += 256) g_cm[i] = 0.f;
    }

    const bf16 *Ah, *Al;
    switch (Asel) {
        case 0: Ah = g_xsh;  Al = g_xsl;  break;
        case 1: Ah = g_qh;   Al = g_ql;   break;
        case 2: Ah = g_opth; Al = g_optl; break;
        case 4: Ah = g_qph;  Al = g_qpl;  break;
        default: Ah = g_ench; Al = g_encl; break;
    }
    float* C;
    switch (Csel) {
        case 0: C = g_h;  break;
        default: C = g_s1; break;
    }
    int bm = blockIdx.y * 128, bn = blockIdx.x * 64;
    const bf16 *Wh, *Wl;
    if (wmode == 1) {
        int slot = (bm < 32000) ? 0 : (bm < 48000) ? 1 : (bm < 56064) ? 2 : (bm < 59392) ? 3 : 4;
        bias += slot * 300;
        Wh = g_wh + slot * WSLOT; Wl = g_wl + slot * WSLOT;
    } else if (wmode == 2) {
        int b = bm >> 11;
        Wh = g_kb1h + b * 64 * KP; Wl = g_kb1l + b * 64 * KP;
    } else if (wmode == 3) {
        int b = bm >> 7;
        Wh = g_kb2h + b * 128 * KP; Wl = g_kb2l + b * 128 * KP;
    } else {
        Wh = g_wh + wslot * WSLOT; Wl = g_wl + wslot * WSLOT;
    }

    int tid = threadIdx.x;
    int lane = tid & 31, warp = tid >> 5;
    int wm = warp & 3, wn = warp >> 2;

    auto issue = [&](int s, int buf) {
        int kt = s * 16;
        bf16* base = sdy + buf * STG;
        int row = tid >> 1, kh = (tid & 1) * 8;
        cp16(base + row * SAST + kh, Ah + (size_t)(bm + row) * KP + kt + kh);
        cp16(base + APL + row * SAST + kh, Al + (size_t)(bm + row) * KP + kt + kh);
        if (tid < 128) {
            int br = tid >> 1, bkh = (tid & 1) * 8;
            cp16(base + 2 * APL + br * SAST + bkh, Wh + (size_t)(bn + br) * KP + kt + bkh);
        } else {
            int t = tid - 128;
            int br = t >> 1, bkh = (t & 1) * 8;
            cp16(base + 2 * APL + BPL + br * SAST + bkh, Wl + (size_t)(bn + br) * KP + kt + bkh);
        }
        asm volatile("cp.async.commit_group;");
    };

    float acc[2][4][4];
    #pragma unroll
    for (int mi = 0; mi < 2; mi++)
        #pragma unroll
        for (int ni = 0; ni < 4; ni++)
            #pragma unroll
            for (int j = 0; j < 4; j++) acc[mi][ni][j] = 0.f;

    unsigned sbase = (unsigned)__cvta_generic_to_shared(sdy);
    unsigned aInv0 = (unsigned)((wm * 32 + (lane & 15)) * SAST + (lane >> 4) * 8);
    unsigned aInv1 = aInv0 + 16 * SAST;
    unsigned bInv0 = (unsigned)(2 * APL +
                     (wn * 32 + ((lane >> 4) & 1) * 8 + (lane & 7)) * SAST + ((lane >> 3) & 1) * 8);
    unsigned bInv1 = bInv0 + 16 * SAST;

    issue(0, 0);
    issue(1, 1);

    for (int s = 0; s < NSTAGE; s++) {
        if (s < NSTAGE - 1) asm volatile("cp.async.wait_group 1;");
        else                asm volatile("cp.async.wait_group 0;");
        __syncthreads();
        int buf = s % 3;
        unsigned bb = (unsigned)(buf * STG);
        unsigned ah[2][4], al[2][4], bh[4][2], bl[4][2];
        ldsm4(ah[0][0], ah[0][1], ah[0][2], ah[0][3], sbase + (bb + aInv0) * 2);
        ldsm4(ah[1][0], ah[1][1], ah[1][2], ah[1][3], sbase + (bb + aInv1) * 2);
        ldsm4(al[0][0], al[0][1], al[0][2], al[0][3], sbase + (bb + APL + aInv0) * 2);
        ldsm4(al[1][0], al[1][1], al[1][2], al[1][3], sbase + (bb + APL + aInv1) * 2);
        ldsm4(bh[0][0], bh[0][1], bh[1][0], bh[1][1], sbase + (bb + bInv0) * 2);
        ldsm4(bh[2][0], bh[2][1], bh[3][0], bh[3][1], sbase + (bb + bInv1) * 2);
        ldsm4(bl[0][0], bl[0][1], bl[1][0], bl[1][1], sbase + (bb + BPL + bInv0) * 2);
        ldsm4(bl[2][0], bl[2][1], bl[3][0], bl[3][1], sbase + (bb + BPL + bInv1) * 2);
        #pragma unroll
        for (int mi = 0; mi < 2; mi++)
            #pragma unroll
            for (int ni = 0; ni < 4; ni++) {
                mma16816(acc[mi][ni], ah[mi], bh[ni]);
                mma16816(acc[mi][ni], ah[mi], bl[ni]);
                mma16816(acc[mi][ni], al[mi], bh[ni]);
            }
        if (s + 2 < NSTAGE) issue(s + 2, (s + 2) % 3);
    }

    // epilogue
    #pragma unroll
    for (int mi = 0; mi < 2; mi++) {
        int mrow = bm + wm * 32 + mi * 16 + (lane >> 2);
        #pragma unroll
        for (int ni = 0; ni < 4; ni++) {
            int ncol = bn + wn * 32 + ni * 8 + 2 * (lane & 3);
            #pragma unroll
            for (int rr = 0; rr < 2; rr++) {
                int m = mrow + rr * 8;
                #pragma unroll
                for (int cc = 0; cc < 2; cc++) {
                    int n = ncol + cc;
                    float v = acc[mi][ni][rr * 2 + cc];
                    if (act == 3) {
                        if (m < M && n < 32) C[(size_t)m * 32 + n] = v;
                    } else if (act == 4) {
                        if (m < 480 && n < 300) {
                            v += __ldg(&bias[n]);
                            int b = m / 30, w = m - b * 30;
                            bf16 hb, lb; split2(v, hb, lb);
                            int o = (b * 64 + w) * KP + n;
                            g_kb1h[o] = hb; g_kb1l[o] = lb;
                        }
                    } else if (act == 5) {
                        if (m < 1024) {
                            int proj = -1, d2 = 0;
                            float bv = 0.f;
                            if (n < 300) { proj = 0; d2 = n; bv = __ldg(&bias[n]); }
                            else if (n >= 320 && n < 620) {
                                proj = 1; d2 = n - 320; bv = __ldg(&bias2[d2]);
                            }
                            if (proj >= 0) {
                                int b = (m >> 4) & 15, opt = m >> 8, w = m & 15;
                                int kk = proj * 64 + opt * 16 + w;
                                bf16 hb, lb; split2(v + bv, hb, lb);
                                int o = (b * 128 + kk) * KP + d2;
                                g_kb2h[o] = hb; g_kb2l[o] = lb;
                            }
                        }
                    } else if (act == 6) {
                        int w1 = m & 127;
                        if (m < 2048 && w1 < 30 && n < 128)
                            g_QK[(m >> 7) * 3840 + w1 * 128 + n] = v;
                    } else if (act == 7) {
                        if (m < M) {
                            if (n < 300) {
                                g_z[(size_t)m * 300 + n] = tanhf(v + __ldg(&bias[n]));
                            } else if (n >= 320 && n < 620) {
                                int n2 = n - 320;
                                g_o[(size_t)m * 300 + n2] = tanhf(v + __ldg(&bias2[n2]));
                            }
                        }
                    } else {
                        if (m < M && n < 300) {
                            v += __ldg(&bias[n]);
                            if (act == 1) v = fmaxf(v, 0.f);
                            else if (act == 2) v = tanhf(v);
                            C[(size_t)m * 300 + n] = v;
                        }
                    }
                }
            }
        }
    }
}

// ---------------- fused gate evaluation ----------------
__device__ __forceinline__ float gate_val(int b, int t, int d, const float* m1,
                                          const float* mb1, const float* m2, float mb2) {
    float y0 = g_h[(b * 2000 + t) * 300 + d];
    float y1 = g_h[(32000 + b * 1000 + (t >> 1)) * 300 + d] * 0.5f;
    float y2 = g_h[(48000 + b * 500 + (t >> 2)) * 300 + d] * 0.25f;
    float y3 = g_h[(56064 + b * 200 + t / 10) * 300 + d] * (1.0f / 10.0f);
    float y4 = g_h[(59392 + b * 80 + t / 25) * 300 + d] * (1.0f / 25.0f);
    float acc = mb2;
    #pragma unroll
    for (int k = 0; k < 3; k++) {
        float hk = mb1[k] + m1[k * 5] * y0 + m1[k * 5 + 1] * y1 + m1[k * 5 + 2] * y2
                 + m1[k * 5 + 3] * y3 + m1[k * 5 + 4] * y4;
        acc += m2[k] * fmaxf(hk, 0.f);
    }
    return fmaxf(acc, 0.f);
}

// ---------------- chunked linear scan (gate fused) ----------------
__global__ void scanA_kernel(const float* __restrict__ mr1W, const float* __restrict__ mr1b,
                             const float* __restrict__ mr2W, const float* __restrict__ mr2b) {
    int ch = blockIdx.x, b = blockIdx.y, d = threadIdx.x;
    float m1[15], mb1[3], m2[3];
    #pragma unroll
    for (int k = 0; k < 15; k++) m1[k] = __ldg(&mr1W[k]);
    #pragma unroll
    for (int k = 0; k < 3; k++) { mb1[k] = __ldg(&mr1b[k]); m2[k] = __ldg(&mr2W[k]); }
    float mb2 = __ldg(mr2b);
    int t0 = ch * 50;
    float a = 1.f, bb = 0.f;
    for (int j = 0; j < 50; j++) {
        float g = gate_val(b, t0 + j, d, m1, mb1, m2, mb2);
        float z = g_z[(b * 2000 + t0 + j) * 300 + d];
        a *= g;
        bb = g * (bb - z) + z;
    }
    int o = (b * 40 + ch) * 300 + d;
    g_scA[o] = a;
    g_scB[o] = bb;
}
__global__ void scanB_kernel() {
    int b = blockIdx.x, d = threadIdx.x;
    float c = 0.f;
    for (int ch = 0; ch < 40; ch++) {
        int o = (b * 40 + ch) * 300 + d;
        g_scC[o] = c;
        c = g_scA[o] * c + g_scB[o];
    }
}
__global__ void scanC_kernel(const float* __restrict__ mr1W, const float* __restrict__ mr1b,
                             const float* __restrict__ mr2W, const float* __restrict__ mr2b) {
    int ch = blockIdx.x, b = blockIdx.y, d = threadIdx.x;
    float m1[15], mb1[3], m2[3];
    #pragma unroll
    for (int k = 0; k < 15; k++) m1[k] = __ldg(&mr1W[k]);
    #pragma unroll
    for (int k = 0; k < 3; k++) { mb1[k] = __ldg(&mr1b[k]); m2[k] = __ldg(&mr2W[k]); }
    float mb2 = __ldg(mr2b);
    float c = g_scC[(b * 40 + ch) * 300 + d];
    int t0 = ch * 50;
    for (int j = 0; j < 50; j++) {
        int t = t0 + j;
        float g = gate_val(b, t, d, m1, mb1, m2, mb2);
        float z = g_z[(b * 2000 + t) * 300 + d];
        c = g * (c - z) + z;
        float enc = g_o[(b * 2000 + t) * 300 + d] * c;
        bf16 hb, lb; split2(enc, hb, lb);
        int o = (b * 2048 + t) * KP + d;
        g_ench[o] = hb; g_encl[o] = lb;
    }
}

// ---------------- fused: softmax30 -> P.QK -> group softmax16 -> column sums ----------------
__global__ void attn_fused() {
    __shared__ float sQK[30 * 128];
    __shared__ float sacc[128];
    int ch = blockIdx.x, b = blockIdx.y;
    int tid = threadIdx.x, warp = tid >> 5, lane = tid & 31;
    for (int i = tid; i < 30 * 128; i += 256) sQK[i] = g_QK[b * 3840 + i];
    if (tid < 128) sacc[tid] = 0.f;
    __syncthreads();
    float lacc[4] = {0.f, 0.f, 0.f, 0.f};
    for (int t = ch * 250 + warp; t < ch * 250 + 250; t += 8) {
        const float* sr = g_s1 + (size_t)(b * 2048 + t) * 32;
        float sc = (lane < 30) ? sr[lane] : -1e30f;
        float mx = sc;
        #pragma unroll
        for (int o = 16; o; o >>= 1) mx = fmaxf(mx, __shfl_xor_sync(0xffffffffu, mx, o));
        float e = (lane < 30) ? expf(sc - mx) : 0.f;
        float sm = e;
        #pragma unroll
        for (int o = 16; o; o >>= 1) sm += __shfl_xor_sync(0xffffffffu, sm, o);
        float p = e / sm;
        float s0 = 0.f, s1v = 0.f, s2v = 0.f, s3v = 0.f;
        #pragma unroll 6
        for (int w = 0; w < 30; w++) {
            float pw = __shfl_sync(0xffffffffu, p, w);
            const float* qk = sQK + w * 128 + lane * 4;
            s0 += pw * qk[0]; s1v += pw * qk[1]; s2v += pw * qk[2]; s3v += pw * qk[3];
        }
        float gm = fmaxf(fmaxf(s0, s1v), fmaxf(s2v, s3v));
        gm = fmaxf(gm, __shfl_xor_sync(0xffffffffu, gm, 1));
        gm = fmaxf(gm, __shfl_xor_sync(0xffffffffu, gm, 2));
        float e0 = expf(s0 - gm), e1 = expf(s1v - gm), e2 = expf(s2v - gm), e3 = expf(s3v - gm);
        float gs = e0 + e1 + e2 + e3;
        gs += __shfl_xor_sync(0xffffffffu, gs, 1);
        gs += __shfl_xor_sync(0xffffffffu, gs, 2);
        float inv = 1.f / gs;
        lacc[0] += e0 * inv; lacc[1] += e1 * inv; lacc[2] += e2 * inv; lacc[3] += e3 * inv;
    }
    #pragma unroll
    for (int j = 0; j < 4; j++) atomicAdd(&sacc[lane * 4 + j], lacc[j]);
    __syncthreads();
    if (tid < 128) {
        int kk = tid;
        int proj = kk >> 6, r = kk & 63;
        int opt = r >> 4, w = r & 15;
        atomicAdd(&g_cm[((opt * 16 + b) * 2 + proj) * 16 + w], sacc[kk]);
    }
}

// ---------------- final MLP ----------------
__global__ void final_kernel(const float* __restrict__ as1W, const float* __restrict__ as1b,
                             const float* __restrict__ as2W, const float* __restrict__ as2b,
                             float* __restrict__ out) {
    __shared__ float sav[600];
    __shared__ float sh[75];
    __shared__ float scm[32];
    int bid = blockIdx.x;
    int opt = bid >> 4, b = bid & 15;
    int ob = opt * 16 + b;
    int tid = threadIdx.x;
    if (tid < 32) scm[tid] = g_cm[ob * 32 + tid] * (1.0f / 2000.0f);
    __syncthreads();
    for (int d = tid; d < 300; d += 128) {
        float a2 = 0.f, a3 = 0.f;
        #pragma unroll
        for (int w = 0; w < 16; w++) {
            float ov = g_optf[(ob * 16 + w) * 300 + d];
            a2 += scm[w] * ov;
            a3 += scm[16 + w] * ov;
        }
        sav[d] = a2;
        sav[300 + d] = a3;
    }
    __syncthreads();
    for (int j = tid; j < 75; j += 128) {
        float a = __ldg(&as1b[j]);
        for (int i2 = 0; i2 < 600; i2++) a += __ldg(&as1W[j * 600 + i2]) * sav[i2];
        sh[j] = fmaxf(a, 0.f);
    }
    __syncthreads();
    if (tid == 0) {
        float s = __ldg(as2b);
        for (int j = 0; j < 75; j++) s += __ldg(&as2W[j]) * sh[j];
        out[b * 4 + opt] = s;
    }
}

// ---------------- launch ----------------
extern "C" void kernel_launch(void* const* d_in, const int* in_sizes, int n_in,
                              void* d_out, int out_size) {
    const int* opt_idx[4] = {(const int*)d_in[0], (const int*)d_in[1],
                             (const int*)d_in[2], (const int*)d_in[3]};
    const int* q_idx = (const int*)d_in[4];
    const int* a_idx = (const int*)d_in[5];
    const float* emb = (const float*)d_in[6];
    const float* ceW = (const float*)d_in[7];
    const float* ceb = (const float*)d_in[8];
    const float* mr1W = (const float*)d_in[9];
    const float* mr1b = (const float*)d_in[10];
    const float* mr2W = (const float*)d_in[11];
    const float* mr2b = (const float*)d_in[12];
    const float* Wz = (const float*)d_in[13];
    const float* bz = (const float*)d_in[14];
    const float* Wo = (const float*)d_in[15];
    const float* bo = (const float*)d_in[16];
    const float* f1W = (const float*)d_in[17];
    const float* f1b = (const float*)d_in[18];
    const float* f2W = (const float*)d_in[19];
    const float* f2b = (const float*)d_in[20];
    const float* f3W = (const float*)d_in[21];
    const float* f3b = (const float*)d_in[22];
    const float* as1W = (const float*)d_in[23];
    const float* as1b = (const float*)d_in[24];
    const float* as2W = (const float*)d_in[25];
    const float* as2b = (const float*)d_in[26];

    static bool attrSet = false;
    if (!attrSet) {
        cudaFuncSetAttribute(gemm_mma, cudaFuncAttributeMaxDynamicSharedMemorySize, GEMM_SMEM);
        attrSet = true;
    }

    // ncu captures 1-indexed launch #4 -> make it the CE GEMM.
    split_w<<<(450000 + 255) / 256, 256>>>(ceW, 0, 450000);                    // 1
    gather_split<<<(32000 * 300 + 255) / 256, 256>>>(a_idx, emb, 0, 0, 32000); // 2
    xs_kernel<<<(28672 * 300 + 255) / 256, 256>>>();                           // 3
    gemm_mma<<<dim3(5, 474), 256, GEMM_SMEM>>>(0, 0, ceb, nullptr, 0, 60672, 1, 1); // 4 <- profiled

    split_w2<<<(180000 + 255) / 256, 256>>>(Wz, Wo, 5);
    gemm_mma<<<dim3(10, 250), 256, GEMM_SMEM>>>(0, 5, bz, bo, 0, 32000, 7, 0);      // z+o

    split_w3<<<(270000 + 255) / 256, 256>>>(f1W, f2W, f3W, 7);
    gather_split<<<(480 * 300 + 255) / 256, 256>>>(q_idx, emb, 1, 0, 480);
    gather_opt4<<<(4 * 256 * 300 + 255) / 256, 256>>>(opt_idx[0], opt_idx[1],
                                                      opt_idx[2], opt_idx[3], emb);

    // chunked scan (gate fused) -> enc split
    scanA_kernel<<<dim3(40, 16), 300>>>(mr1W, mr1b, mr2W, mr2b);
    scanB_kernel<<<16, 300>>>();
    scanC_kernel<<<dim3(40, 16), 300>>>(mr1W, mr1b, mr2W, mr2b);

    // f1 keys (split, per-batch) then attn1 scores GEMM
    gemm_mma<<<dim3(5, 4), 256, GEMM_SMEM>>>(1, 7, f1b, nullptr, 0, 480, 4, 0);
    gemm_mma<<<dim3(1, 256), 256, GEMM_SMEM>>>(3, 0, nullptr, nullptr, 5, 32768, 3, 2);

    // merged f2+f3 option keys, then QK GEMM (zeroes g_cm) + fused attention-2
    gemm_mma<<<dim3(10, 8), 256, GEMM_SMEM>>>(2, 8, f2b, f3b, 0, 1024, 5, 0);
    gemm_mma<<<dim3(2, 16), 256, GEMM_SMEM>>>(4, 0, nullptr, nullptr, 5, 2048, 6, 3);
    attn_fused<<<dim3(8, 16), 256>>>();

    // final MLP
    final_kernel<<<64, 128>>>(as1W, as1b, as2W, as2b, (float*)d_out);
}

// round 17
// speedup vs baseline: 1.6607x; 1.0423x over previous
#include <cuda_runtime.h>
#include <cuda_bf16.h>
#include <math.h>

// DIM=300 (K padded to 304 = 19 k16 stages), B=16, T=2000, Tq=30, Topt=16
#define KP 304
#define NSTAGE 19
// CE padded row layout (128-aligned range starts): 0,32000,48000,56064,59392; M=60672

typedef __nv_bfloat16 bf16;

// ---------------- scratch ----------------
__device__ bf16  g_xsh[60672 * KP], g_xsl[60672 * KP];   // rows 0..32000 = article split
__device__ float g_h[60672 * 300];
__device__ float g_z[32000 * 300];
__device__ float g_o[32000 * 300];
__device__ bf16  g_ench[32768 * KP], g_encl[32768 * KP]; // rows b*2048+t (pad rows stay 0)
__device__ float g_s1[32768 * 32];                       // attn1 scores
__device__ bf16  g_qh[512 * KP], g_ql[512 * KP];         // rows b*30+w (f1-keys GEMM A)
__device__ bf16  g_qph[2048 * KP], g_qpl[2048 * KP];     // rows b*128+w1 (QK GEMM A, pads 0)
__device__ float g_optf[1024 * 300];
__device__ bf16  g_opth[1024 * KP], g_optl[1024 * KP];
__device__ bf16  g_kb1h[16 * 64 * KP], g_kb1l[16 * 64 * KP];   // f1 keys per batch (rows 30..63 zero)
__device__ bf16  g_kb2h[16 * 128 * KP], g_kb2l[16 * 128 * KP]; // f2/f3 keys per batch
__device__ float g_QK[16 * 30 * 128];
__device__ float g_scA[16 * 40 * 300], g_scB[16 * 40 * 300], g_scC[16 * 40 * 300];
__device__ float g_cm[4 * 16 * 2 * 16];
// weight slots [320][KP]: 0-4 ce, 5 Wz, 6 Wo, 7 f1, 8 f2, 9 f3
#define WSLOT (320 * KP)
__device__ bf16 g_wh[10 * WSLOT], g_wl[10 * WSLOT];

// ---------------- helpers ----------------
__device__ __forceinline__ void split2(float x, bf16& h, bf16& l) {
    h = __float2bfloat16(x);
    l = __float2bfloat16(x - __bfloat162float(h));
}
__device__ __forceinline__ void cp16(void* s, const void* g) {
    unsigned sa = (unsigned)__cvta_generic_to_shared(s);
    asm volatile("cp.async.cg.shared.global [%0], [%1], 16;" :: "r"(sa), "l"(g));
}
__device__ __forceinline__ void mma16816(float* c, const unsigned* a, const unsigned* b) {
    asm volatile(
        "mma.sync.aligned.m16n8k16.row.col.f32.bf16.bf16.f32 "
        "{%0,%1,%2,%3}, {%4,%5,%6,%7}, {%8,%9}, {%0,%1,%2,%3};\n"
        : "+f"(c[0]), "+f"(c[1]), "+f"(c[2]), "+f"(c[3])
        : "r"(a[0]), "r"(a[1]), "r"(a[2]), "r"(a[3]), "r"(b[0]), "r"(b[1]));
}
__device__ __forceinline__ void ldsm4(unsigned& r0, unsigned& r1, unsigned& r2, unsigned& r3,
                                      unsigned addr) {
    asm volatile("ldmatrix.sync.aligned.m8n8.x4.shared.b16 {%0,%1,%2,%3}, [%4];"
                 : "=r"(r0), "=r"(r1), "=r"(r2), "=r"(r3) : "r"(addr));
}

// ---------------- weight prep: all 10 slots in one launch ----------------
__global__ void split_all(const float* __restrict__ ceW, const float* __restrict__ Wz,
                          const float* __restrict__ Wo, const float* __restrict__ f1W,
                          const float* __restrict__ f2W, const float* __restrict__ f3W) {
    int i = blockIdx.x * blockDim.x + threadIdx.x;
    if (i >= 900000) return;
    int slot = i / 90000, rem = i % 90000;
    const float* src;
    if (slot < 5) src = ceW + slot * 90000;
    else if (slot == 5) src = Wz;
    else if (slot == 6) src = Wo;
    else if (slot == 7) src = f1W;
    else if (slot == 8) src = f2W;
    else src = f3W;
    float x = src[rem];
    int n = rem / 300, k = rem - n * 300;
    bf16 h, l; split2(x, h, l);
    int o = slot * WSLOT + n * KP + k;
    g_wh[o] = h; g_wl[o] = l;
}

// ---------------- embedding gathers ----------------
__global__ void gather_art(const int* __restrict__ idx, const float* __restrict__ emb) {
    int i = blockIdx.x * blockDim.x + threadIdx.x;
    if (i >= 32000 * 300) return;
    int r = i / 300, d = i - r * 300;
    float x = emb[idx[r] * 300 + d];
    bf16 hb, lb; split2(x, hb, lb);
    g_xsh[r * KP + d] = hb; g_xsl[r * KP + d] = lb;
}
__global__ void gather_qopt(const int* __restrict__ q_idx, const int* __restrict__ i0,
                            const int* __restrict__ i1, const int* __restrict__ i2,
                            const int* __restrict__ i3, const float* __restrict__ emb) {
    int i = blockIdx.x * blockDim.x + threadIdx.x;
    if (i < 480 * 300) {  // question
        int r = i / 300, d = i - r * 300;
        float x = emb[q_idx[r] * 300 + d];
        bf16 hb, lb; split2(x, hb, lb);
        g_qh[r * KP + d] = hb; g_ql[r * KP + d] = lb;
        int b = r / 30, w1 = r - b * 30;
        int o = (b * 128 + w1) * KP + d;
        g_qph[o] = hb; g_qpl[o] = lb;
        return;
    }
    int j = i - 480 * 300;
    if (j >= 4 * 256 * 300) return;
    int opt = j / 76800;
    int rem = j - opt * 76800;
    int r = rem / 300, d = rem - r * 300;
    const int* ip = (opt == 0) ? i0 : (opt == 1) ? i1 : (opt == 2) ? i2 : i3;
    float x = emb[ip[r] * 300 + d];
    int R = opt * 256 + r;
    bf16 hb, lb; split2(x, hb, lb);
    g_optf[R * 300 + d] = x;
    g_opth[R * KP + d] = hb; g_optl[R * KP + d] = lb;
}

// ---------------- group sums for r>=2 ranges (reads article from split rows) ----------------
__device__ __forceinline__ float artval(int row, int d) {
    int o = row * KP + d;
    return __bfloat162float(g_xsh[o]) + __bfloat162float(g_xsl[o]);
}
__global__ void xs_kernel() {
    int i = blockIdx.x * blockDim.x + threadIdx.x;
    if (i >= 28672 * 300) return;
    int R = 32000 + i / 300, d = i % 300;
    float s;
    if (R < 48000) {
        int L = R - 32000, b = L / 1000, g = L - b * 1000;
        int base = b * 2000 + g * 2;
        s = artval(base, d) + artval(base + 1, d);
    } else if (R < 56000) {
        int L = R - 48000, b = L / 500, g = L - b * 500;
        int base = b * 2000 + g * 4;
        s = 0.f;
        #pragma unroll
        for (int j = 0; j < 4; j++) s += artval(base + j, d);
    } else if (R < 56064) return;
    else if (R < 59264) {
        int L = R - 56064, b = L / 200, g = L - b * 200;
        int base = b * 2000 + g * 10;
        s = 0.f;
        #pragma unroll
        for (int j = 0; j < 10; j++) s += artval(base + j, d);
    } else if (R < 59392) return;
    else {
        int L = R - 59392, b = L / 80, g = L - b * 80;
        int base = b * 2000 + g * 25;
        s = 0.f;
        #pragma unroll
        for (int j = 0; j < 25; j++) s += artval(base + j, d);
    }
    bf16 h, l; split2(s, h, l);
    g_xsh[R * KP + d] = h;
    g_xsl[R * KP + d] = l;
}

// ---------------- tensor-core GEMM (dual-config per launch) ----------------
// C = act(A(M,300) @ W(300,300)^T + bias); bf16 2-split (hh+hl+lh).
// 3-stage cp.async pipeline, ldmatrix fragment loads, one __syncthreads per stage.
// Blocks with blockIdx.y < ySplit use config 1 (x-tiles limited to nx1), else config 2.
// wmode: 0 slot, 1 CE per-range, 2 f1 keys per batch (bm>>11), 3 f2/f3 keys per batch (bm>>7)
// act: 0 none /1 relu /2 tanh (fp32 C stride 300); 3 scores (fp32 stride 32, n<32);
//      4 f1-key split -> g_kb1 (bias); 5 f2/f3-key split -> g_kb2 (bias/bias2 per col);
//      6 QK epilogue -> g_QK (zeroes g_cm from by==ySplit);
//      7 merged z/o: cols 0-299 -> z (bias), 320-619 -> o (bias2)
#define SAST 24
#define APL (128 * SAST)
#define BPL (64 * SAST)
#define STG (2 * APL + 2 * BPL)
#define GEMM_SMEM (3 * STG * 2)

__global__ void __launch_bounds__(256) gemm_mma(
    int ySplit, int nx1,
    int Asel1, int wslot1, int act1c, int wmode1c, int Csel1, int M1,
    const float* __restrict__ b1a, const float* __restrict__ b1b,
    int Asel2, int wslot2, int act2c, int wmode2c, int Csel2, int M2,
    const float* __restrict__ b2a, const float* __restrict__ b2b) {
    extern __shared__ __align__(16) bf16 sdy[];

    int by = blockIdx.y;
    int Asel, wslot, act, wmode, Csel, M, bm;
    const float *bias, *bias2;
    if (by < ySplit) {
        if ((int)blockIdx.x >= nx1) return;
        Asel = Asel1; wslot = wslot1; act = act1c; wmode = wmode1c;
        Csel = Csel1; M = M1; bias = b1a; bias2 = b1b;
        bm = by * 128;
    } else {
        Asel = Asel2; wslot = wslot2; act = act2c; wmode = wmode2c;
        Csel = Csel2; M = M2; bias = b2a; bias2 = b2b;
        bm = (by - ySplit) * 128;
    }

    if (act == 6 && by == ySplit) {  // fold g_cm zeroing into the QK blocks
        for (int i = threadIdx.x; i < 2048; i += 256) g_cm[i] = 0.f;
    }

    const bf16 *Ah, *Al;
    switch (Asel) {
        case 0: Ah = g_xsh;  Al = g_xsl;  break;
        case 1: Ah = g_qh;   Al = g_ql;   break;
        case 2: Ah = g_opth; Al = g_optl; break;
        case 4: Ah = g_qph;  Al = g_qpl;  break;
        default: Ah = g_ench; Al = g_encl; break;
    }
    float* C;
    switch (Csel) {
        case 0: C = g_h;  break;
        default: C = g_s1; break;
    }
    int bn = blockIdx.x * 64;
    const bf16 *Wh, *Wl;
    if (wmode == 1) {
        int slot = (bm < 32000) ? 0 : (bm < 48000) ? 1 : (bm < 56064) ? 2 : (bm < 59392) ? 3 : 4;
        bias += slot * 300;
        Wh = g_wh + slot * WSLOT; Wl = g_wl + slot * WSLOT;
    } else if (wmode == 2) {
        int b = bm >> 11;
        Wh = g_kb1h + b * 64 * KP; Wl = g_kb1l + b * 64 * KP;
    } else if (wmode == 3) {
        int b = bm >> 7;
        Wh = g_kb2h + b * 128 * KP; Wl = g_kb2l + b * 128 * KP;
    } else {
        Wh = g_wh + wslot * WSLOT; Wl = g_wl + wslot * WSLOT;
    }

    int tid = threadIdx.x;
    int lane = tid & 31, warp = tid >> 5;
    int wm = warp & 3, wn = warp >> 2;

    auto issue = [&](int s, int buf) {
        int kt = s * 16;
        bf16* base = sdy + buf * STG;
        int row = tid >> 1, kh = (tid & 1) * 8;
        cp16(base + row * SAST + kh, Ah + (size_t)(bm + row) * KP + kt + kh);
        cp16(base + APL + row * SAST + kh, Al + (size_t)(bm + row) * KP + kt + kh);
        if (tid < 128) {
            int br = tid >> 1, bkh = (tid & 1) * 8;
            cp16(base + 2 * APL + br * SAST + bkh, Wh + (size_t)(bn + br) * KP + kt + bkh);
        } else {
            int t = tid - 128;
            int br = t >> 1, bkh = (t & 1) * 8;
            cp16(base + 2 * APL + BPL + br * SAST + bkh, Wl + (size_t)(bn + br) * KP + kt + bkh);
        }
        asm volatile("cp.async.commit_group;");
    };

    float acc[2][4][4];
    #pragma unroll
    for (int mi = 0; mi < 2; mi++)
        #pragma unroll
        for (int ni = 0; ni < 4; ni++)
            #pragma unroll
            for (int j = 0; j < 4; j++) acc[mi][ni][j] = 0.f;

    unsigned sbase = (unsigned)__cvta_generic_to_shared(sdy);
    unsigned aInv0 = (unsigned)((wm * 32 + (lane & 15)) * SAST + (lane >> 4) * 8);
    unsigned aInv1 = aInv0 + 16 * SAST;
    unsigned bInv0 = (unsigned)(2 * APL +
                     (wn * 32 + ((lane >> 4) & 1) * 8 + (lane & 7)) * SAST + ((lane >> 3) & 1) * 8);
    unsigned bInv1 = bInv0 + 16 * SAST;

    issue(0, 0);
    issue(1, 1);

    for (int s = 0; s < NSTAGE; s++) {
        if (s < NSTAGE - 1) asm volatile("cp.async.wait_group 1;");
        else                asm volatile("cp.async.wait_group 0;");
        __syncthreads();
        int buf = s % 3;
        unsigned bb = (unsigned)(buf * STG);
        unsigned ah[2][4], al[2][4], bh[4][2], bl[4][2];
        ldsm4(ah[0][0], ah[0][1], ah[0][2], ah[0][3], sbase + (bb + aInv0) * 2);
        ldsm4(ah[1][0], ah[1][1], ah[1][2], ah[1][3], sbase + (bb + aInv1) * 2);
        ldsm4(al[0][0], al[0][1], al[0][2], al[0][3], sbase + (bb + APL + aInv0) * 2);
        ldsm4(al[1][0], al[1][1], al[1][2], al[1][3], sbase + (bb + APL + aInv1) * 2);
        ldsm4(bh[0][0], bh[0][1], bh[1][0], bh[1][1], sbase + (bb + bInv0) * 2);
        ldsm4(bh[2][0], bh[2][1], bh[3][0], bh[3][1], sbase + (bb + bInv1) * 2);
        ldsm4(bl[0][0], bl[0][1], bl[1][0], bl[1][1], sbase + (bb + BPL + bInv0) * 2);
        ldsm4(bl[2][0], bl[2][1], bl[3][0], bl[3][1], sbase + (bb + BPL + bInv1) * 2);
        #pragma unroll
        for (int mi = 0; mi < 2; mi++)
            #pragma unroll
            for (int ni = 0; ni < 4; ni++) {
                mma16816(acc[mi][ni], ah[mi], bh[ni]);
                mma16816(acc[mi][ni], ah[mi], bl[ni]);
                mma16816(acc[mi][ni], al[mi], bh[ni]);
            }
        if (s + 2 < NSTAGE) issue(s + 2, (s + 2) % 3);
    }

    // epilogue
    #pragma unroll
    for (int mi = 0; mi < 2; mi++) {
        int mrow = bm + wm * 32 + mi * 16 + (lane >> 2);
        #pragma unroll
        for (int ni = 0; ni < 4; ni++) {
            int ncol = bn + wn * 32 + ni * 8 + 2 * (lane & 3);
            #pragma unroll
            for (int rr = 0; rr < 2; rr++) {
                int m = mrow + rr * 8;
                #pragma unroll
                for (int cc = 0; cc < 2; cc++) {
                    int n = ncol + cc;
                    float v = acc[mi][ni][rr * 2 + cc];
                    if (act == 3) {
                        if (m < M && n < 32) C[(size_t)m * 32 + n] = v;
                    } else if (act == 4) {
                        if (m < 480 && n < 300) {
                            v += __ldg(&bias[n]);
                            int b = m / 30, w = m - b * 30;
                            bf16 hb, lb; split2(v, hb, lb);
                            int o = (b * 64 + w) * KP + n;
                            g_kb1h[o] = hb; g_kb1l[o] = lb;
                        }
                    } else if (act == 5) {
                        if (m < 1024) {
                            int proj = -1, d2 = 0;
                            float bv = 0.f;
                            if (n < 300) { proj = 0; d2 = n; bv = __ldg(&bias[n]); }
                            else if (n >= 320 && n < 620) {
                                proj = 1; d2 = n - 320; bv = __ldg(&bias2[d2]);
                            }
                            if (proj >= 0) {
                                int b = (m >> 4) & 15, opt = m >> 8, w = m & 15;
                                int kk = proj * 64 + opt * 16 + w;
                                bf16 hb, lb; split2(v + bv, hb, lb);
                                int o = (b * 128 + kk) * KP + d2;
                                g_kb2h[o] = hb; g_kb2l[o] = lb;
                            }
                        }
                    } else if (act == 6) {
                        int w1 = m & 127;
                        if (m < 2048 && w1 < 30 && n < 128)
                            g_QK[(m >> 7) * 3840 + w1 * 128 + n] = v;
                    } else if (act == 7) {
                        if (m < M) {
                            if (n < 300) {
                                g_z[(size_t)m * 300 + n] = tanhf(v + __ldg(&bias[n]));
                            } else if (n >= 320 && n < 620) {
                                int n2 = n - 320;
                                g_o[(size_t)m * 300 + n2] = tanhf(v + __ldg(&bias2[n2]));
                            }
                        }
                    } else {
                        if (m < M && n < 300) {
                            v += __ldg(&bias[n]);
                            if (act == 1) v = fmaxf(v, 0.f);
                            else if (act == 2) v = tanhf(v);
                            C[(size_t)m * 300 + n] = v;
                        }
                    }
                }
            }
        }
    }
}

// ---------------- fused gate evaluation ----------------
__device__ __forceinline__ float gate_val(int b, int t, int d, const float* m1,
                                          const float* mb1, const float* m2, float mb2) {
    float y0 = g_h[(b * 2000 + t) * 300 + d];
    float y1 = g_h[(32000 + b * 1000 + (t >> 1)) * 300 + d] * 0.5f;
    float y2 = g_h[(48000 + b * 500 + (t >> 2)) * 300 + d] * 0.25f;
    float y3 = g_h[(56064 + b * 200 + t / 10) * 300 + d] * (1.0f / 10.0f);
    float y4 = g_h[(59392 + b * 80 + t / 25) * 300 + d] * (1.0f / 25.0f);
    float acc = mb2;
    #pragma unroll
    for (int k = 0; k < 3; k++) {
        float hk = mb1[k] + m1[k * 5] * y0 + m1[k * 5 + 1] * y1 + m1[k * 5 + 2] * y2
                 + m1[k * 5 + 3] * y3 + m1[k * 5 + 4] * y4;
        acc += m2[k] * fmaxf(hk, 0.f);
    }
    return fmaxf(acc, 0.f);
}

// ---------------- chunked linear scan (gate fused) ----------------
__global__ void scanA_kernel(const float* __restrict__ mr1W, const float* __restrict__ mr1b,
                             const float* __restrict__ mr2W, const float* __restrict__ mr2b) {
    int ch = blockIdx.x, b = blockIdx.y, d = threadIdx.x;
    float m1[15], mb1[3], m2[3];
    #pragma unroll
    for (int k = 0; k < 15; k++) m1[k] = __ldg(&mr1W[k]);
    #pragma unroll
    for (int k = 0; k < 3; k++) { mb1[k] = __ldg(&mr1b[k]); m2[k] = __ldg(&mr2W[k]); }
    float mb2 = __ldg(mr2b);
    int t0 = ch * 50;
    float a = 1.f, bb = 0.f;
    for (int j = 0; j < 50; j++) {
        float g = gate_val(b, t0 + j, d, m1, mb1, m2, mb2);
        float z = g_z[(b * 2000 + t0 + j) * 300 + d];
        a *= g;
        bb = g * (bb - z) + z;
    }
    int o = (b * 40 + ch) * 300 + d;
    g_scA[o] = a;
    g_scB[o] = bb;
}
__global__ void scanB_kernel() {
    int b = blockIdx.x, d = threadIdx.x;
    float c = 0.f;
    for (int ch = 0; ch < 40; ch++) {
        int o = (b * 40 + ch) * 300 + d;
        g_scC[o] = c;
        c = g_scA[o] * c + g_scB[o];
    }
}
__global__ void scanC_kernel(const float* __restrict__ mr1W, const float* __restrict__ mr1b,
                             const float* __restrict__ mr2W, const float* __restrict__ mr2b) {
    int ch = blockIdx.x, b = blockIdx.y, d = threadIdx.x;
    float m1[15], mb1[3], m2[3];
    #pragma unroll
    for (int k = 0; k < 15; k++) m1[k] = __ldg(&mr1W[k]);
    #pragma unroll
    for (int k = 0; k < 3; k++) { mb1[k] = __ldg(&mr1b[k]); m2[k] = __ldg(&mr2W[k]); }
    float mb2 = __ldg(mr2b);
    float c = g_scC[(b * 40 + ch) * 300 + d];
    int t0 = ch * 50;
    for (int j = 0; j < 50; j++) {
        int t = t0 + j;
        float g = gate_val(b, t, d, m1, mb1, m2, mb2);
        float z = g_z[(b * 2000 + t) * 300 + d];
        c = g * (c - z) + z;
        float enc = g_o[(b * 2000 + t) * 300 + d] * c;
        bf16 hb, lb; split2(enc, hb, lb);
        int o = (b * 2048 + t) * KP + d;
        g_ench[o] = hb; g_encl[o] = lb;
    }
}

// ---------------- fused: softmax30 -> P.QK -> group softmax16 -> column sums ----------------
__global__ void attn_fused() {
    __shared__ float sQK[30 * 128];
    __shared__ float sacc[128];
    int ch = blockIdx.x, b = blockIdx.y;
    int tid = threadIdx.x, warp = tid >> 5, lane = tid & 31;
    for (int i = tid; i < 30 * 128; i += 256) sQK[i] = g_QK[b * 3840 + i];
    if (tid < 128) sacc[tid] = 0.f;
    __syncthreads();
    float lacc[4] = {0.f, 0.f, 0.f, 0.f};
    for (int t = ch * 250 + warp; t < ch * 250 + 250; t += 8) {
        const float* sr = g_s1 + (size_t)(b * 2048 + t) * 32;
        float sc = (lane < 30) ? sr[lane] : -1e30f;
        float mx = sc;
        #pragma unroll
        for (int o = 16; o; o >>= 1) mx = fmaxf(mx, __shfl_xor_sync(0xffffffffu, mx, o));
        float e = (lane < 30) ? expf(sc - mx) : 0.f;
        float sm = e;
        #pragma unroll
        for (int o = 16; o; o >>= 1) sm += __shfl_xor_sync(0xffffffffu, sm, o);
        float p = e / sm;
        float s0 = 0.f, s1v = 0.f, s2v = 0.f, s3v = 0.f;
        #pragma unroll 6
        for (int w = 0; w < 30; w++) {
            float pw = __shfl_sync(0xffffffffu, p, w);
            const float* qk = sQK + w * 128 + lane * 4;
            s0 += pw * qk[0]; s1v += pw * qk[1]; s2v += pw * qk[2]; s3v += pw * qk[3];
        }
        float gm = fmaxf(fmaxf(s0, s1v), fmaxf(s2v, s3v));
        gm = fmaxf(gm, __shfl_xor_sync(0xffffffffu, gm, 1));
        gm = fmaxf(gm, __shfl_xor_sync(0xffffffffu, gm, 2));
        float e0 = expf(s0 - gm), e1 = expf(s1v - gm), e2 = expf(s2v - gm), e3 = expf(s3v - gm);
        float gs = e0 + e1 + e2 + e3;
        gs += __shfl_xor_sync(0xffffffffu, gs, 1);
        gs += __shfl_xor_sync(0xffffffffu, gs, 2);
        float inv = 1.f / gs;
        lacc[0] += e0 * inv; lacc[1] += e1 * inv; lacc[2] += e2 * inv; lacc[3] += e3 * inv;
    }
    #pragma unroll
    for (int j = 0; j < 4; j++) atomicAdd(&sacc[lane * 4 + j], lacc[j]);
    __syncthreads();
    if (tid < 128) {
        int kk = tid;
        int proj = kk >> 6, r = kk & 63;
        int opt = r >> 4, w = r & 15;
        atomicAdd(&g_cm[((opt * 16 + b) * 2 + proj) * 16 + w], sacc[kk]);
    }
}

// ---------------- final MLP ----------------
__global__ void final_kernel(const float* __restrict__ as1W, const float* __restrict__ as1b,
                             const float* __restrict__ as2W, const float* __restrict__ as2b,
                             float* __restrict__ out) {
    __shared__ float sav[600];
    __shared__ float sh[75];
    __shared__ float scm[32];
    int bid = blockIdx.x;
    int opt = bid >> 4, b = bid & 15;
    int ob = opt * 16 + b;
    int tid = threadIdx.x;
    if (tid < 32) scm[tid] = g_cm[ob * 32 + tid] * (1.0f / 2000.0f);
    __syncthreads();
    for (int d = tid; d < 300; d += 128) {
        float a2 = 0.f, a3 = 0.f;
        #pragma unroll
        for (int w = 0; w < 16; w++) {
            float ov = g_optf[(ob * 16 + w) * 300 + d];
            a2 += scm[w] * ov;
            a3 += scm[16 + w] * ov;
        }
        sav[d] = a2;
        sav[300 + d] = a3;
    }
    __syncthreads();
    for (int j = tid; j < 75; j += 128) {
        float a = __ldg(&as1b[j]);
        for (int i2 = 0; i2 < 600; i2++) a += __ldg(&as1W[j * 600 + i2]) * sav[i2];
        sh[j] = fmaxf(a, 0.f);
    }
    __syncthreads();
    if (tid == 0) {
        float s = __ldg(as2b);
        for (int j = 0; j < 75; j++) s += __ldg(&as2W[j]) * sh[j];
        out[b * 4 + opt] = s;
    }
}

// ---------------- launch ----------------
extern "C" void kernel_launch(void* const* d_in, const int* in_sizes, int n_in,
                              void* d_out, int out_size) {
    const int* opt_idx[4] = {(const int*)d_in[0], (const int*)d_in[1],
                             (const int*)d_in[2], (const int*)d_in[3]};
    const int* q_idx = (const int*)d_in[4];
    const int* a_idx = (const int*)d_in[5];
    const float* emb = (const float*)d_in[6];
    const float* ceW = (const float*)d_in[7];
    const float* ceb = (const float*)d_in[8];
    const float* mr1W = (const float*)d_in[9];
    const float* mr1b = (const float*)d_in[10];
    const float* mr2W = (const float*)d_in[11];
    const float* mr2b = (const float*)d_in[12];
    const float* Wz = (const float*)d_in[13];
    const float* bz = (const float*)d_in[14];
    const float* Wo = (const float*)d_in[15];
    const float* bo = (const float*)d_in[16];
    const float* f1W = (const float*)d_in[17];
    const float* f1b = (const float*)d_in[18];
    const float* f2W = (const float*)d_in[19];
    const float* f2b = (const float*)d_in[20];
    const float* f3W = (const float*)d_in[21];
    const float* f3b = (const float*)d_in[22];
    const float* as1W = (const float*)d_in[23];
    const float* as1b = (const float*)d_in[24];
    const float* as2W = (const float*)d_in[25];
    const float* as2b = (const float*)d_in[26];

    static bool attrSet = false;
    if (!attrSet) {
        cudaFuncSetAttribute(gemm_mma, cudaFuncAttributeMaxDynamicSharedMemorySize, GEMM_SMEM);
        attrSet = true;
    }

    // 1-3: prep; #4 = mega GEMM (profiled by ncu -s 5 -c 1 -> 1-indexed launch #4)
    split_all<<<(900000 + 255) / 256, 256>>>(ceW, Wz, Wo, f1W, f2W, f3W);       // 1
    gather_art<<<(32000 * 300 + 255) / 256, 256>>>(a_idx, emb);                 // 2
    xs_kernel<<<(28672 * 300 + 255) / 256, 256>>>();                            // 3
    // 4: CE (474 rows, 5 N-tiles) + merged z/o (250 rows, 10 N-tiles)
    gemm_mma<<<dim3(10, 724), 256, GEMM_SMEM>>>(
        474, 5,
        0, 0, 1, 1, 0, 60672, ceb, nullptr,
        0, 5, 7, 0, 0, 32000, bz, bo);

    // q + option gathers (one launch)
    gather_qopt<<<((480 + 1024) * 300 + 255) / 256, 256>>>(
        q_idx, opt_idx[0], opt_idx[1], opt_idx[2], opt_idx[3], emb);

    // chunked scan (gate fused) -> enc split
    scanA_kernel<<<dim3(40, 16), 300>>>(mr1W, mr1b, mr2W, mr2b);
    scanB_kernel<<<16, 300>>>();
    scanC_kernel<<<dim3(40, 16), 300>>>(mr1W, mr1b, mr2W, mr2b);

    // merged key projections: f1 keys (4 rows, 5 tiles) + f2/f3 keys (8 rows, 10 tiles)
    gemm_mma<<<dim3(10, 12), 256, GEMM_SMEM>>>(
        4, 5,
        1, 7, 4, 0, 0, 480, f1b, nullptr,
        2, 8, 5, 0, 0, 1024, f2b, f3b);

    // merged attn1 scores (256 rows, 1 tile) + QK (16 rows, 2 tiles; zeroes g_cm)
    gemm_mma<<<dim3(2, 272), 256, GEMM_SMEM>>>(
        256, 1,
        3, 0, 3, 2, 1, 32768, nullptr, nullptr,
        4, 0, 6, 3, 1, 2048, nullptr, nullptr);

    attn_fused<<<dim3(8, 16), 256>>>();
    final_kernel<<<64, 128>>>(as1W, as1b, as2W, as2b, (float*)d_out);
}